// round 4
// baseline (speedup 1.0000x reference)
#include <cuda_runtime.h>

#define W 512
#define PLANE (512*512)
#define NPLANES 32
#define HALF 16
#define TOTAL (NPLANES*PLANE)
#define IMG_ELEMS (HALF*PLANE)   // 4,194,304 per input tensor
#define TS 64
#define NT 256
#define RED_BLOCKS 2048
#define N_ITER 20

// Scratch: device globals (no allocation allowed).
__device__ float g_bufA[TOTAL];
__device__ float g_bufB[TOTAL];
__device__ float g_skel[TOTAL];
__device__ float g_part[RED_BLOCKS * 8];

__device__ __forceinline__ float gelu_exact(float x) {
    // torch F.gelu default: 0.5*x*(1+erf(x/sqrt(2)))
    return 0.5f * x * (1.0f + erff(x * 0.70710678118654752f));
}

// ---------------------------------------------------------------------------
// INIT: skel = gelu(img - dilate(erode(img))); bufA = img
// Halo 2. Planes 0..15 = y_pred, 16..31 = y_true.
// ---------------------------------------------------------------------------
__global__ __launch_bounds__(NT) void init_kernel(const float* __restrict__ y_true,
                                                  const float* __restrict__ y_pred) {
    __shared__ float s_img[68 * 69];   // tile + halo2, pitch 69
    __shared__ float s_e1[66 * 67];    // erode(img) on T+1, pitch 67

    const int plane = blockIdx.z;
    const float* src = ((plane < HALF) ? y_pred : y_true) + (plane & 15) * PLANE;
    const int by = blockIdx.y * TS, bx = blockIdx.x * TS;
    const int tid = threadIdx.x;
    const float BIG = 1e30f;

    // Load img with halo 2; out-of-image -> +BIG (erode pads +inf)
    for (int i = tid; i < 68 * 68; i += NT) {
        int r = i / 68, c = i - r * 68;
        int gr = by + r - 2, gc = bx + c - 2;
        float v = BIG;
        if ((unsigned)gr < 512u && (unsigned)gc < 512u) v = src[gr * W + gc];
        s_img[r * 69 + c] = v;
    }
    __syncthreads();

    // E1 = erode(img) on T+1; out-of-image -> -BIG (feeds dilate, pads -inf)
    for (int i = tid; i < 66 * 66; i += NT) {
        int r = i / 66, c = i - r * 66;
        int gr = by + r - 1, gc = bx + c - 1;
        float v = -BIG;
        if ((unsigned)gr < 512u && (unsigned)gc < 512u) {
            int rr = r + 1, cc = c + 1;
            float ce = s_img[rr * 69 + cc];
            v = fminf(ce, fminf(fminf(s_img[(rr - 1) * 69 + cc], s_img[(rr + 1) * 69 + cc]),
                                fminf(s_img[rr * 69 + cc - 1], s_img[rr * 69 + cc + 1])));
        }
        s_e1[r * 67 + c] = v;
    }
    __syncthreads();

    // open = dilate(E1); skel = gelu(img - open); bufA = img
    for (int i = tid; i < TS * TS; i += NT) {
        int r = i >> 6, c = i & 63;
        float m = -BIG;
        #pragma unroll
        for (int dr = 0; dr < 3; dr++)
            #pragma unroll
            for (int dc = 0; dc < 3; dc++)
                m = fmaxf(m, s_e1[(r + dr) * 67 + c + dc]);
        float img = s_img[(r + 2) * 69 + (c + 2)];
        int g = plane * PLANE + (by + r) * W + (bx + c);
        g_skel[g] = gelu_exact(img - m);
        g_bufA[g] = img;
    }
}

// ---------------------------------------------------------------------------
// STEP: img' = erode(img); delta = gelu(img' - dilate(erode(img')));
//       skel += gelu(delta - skel*delta)
// Halo 3. E2 reuses s_img storage (keeps static smem under 48 KB).
// ---------------------------------------------------------------------------
__global__ __launch_bounds__(NT) void step_kernel(int readA) {
    __shared__ float s_img[70 * 71];   // tile + halo3, pitch 71; later reused as E2 (pitch 67)
    __shared__ float s_e1[68 * 69];    // erode(img) on T+2, pitch 69

    const float* src = readA ? g_bufA : g_bufB;
    float*       dst = readA ? g_bufB : g_bufA;
    const int plane = blockIdx.z;
    const float* sp = src + plane * PLANE;
    const int by = blockIdx.y * TS, bx = blockIdx.x * TS;
    const int tid = threadIdx.x;
    const float BIG = 1e30f;

    // Load img with halo 3; out-of-image -> +BIG
    for (int i = tid; i < 70 * 70; i += NT) {
        int r = i / 70, c = i - r * 70;
        int gr = by + r - 3, gc = bx + c - 3;
        float v = BIG;
        if ((unsigned)gr < 512u && (unsigned)gc < 512u) v = sp[gr * W + gc];
        s_img[r * 71 + c] = v;
    }
    __syncthreads();

    // E1 = erode(img) on T+2; out-of-image -> +BIG (feeds second erode)
    for (int i = tid; i < 68 * 68; i += NT) {
        int r = i / 68, c = i - r * 68;
        int gr = by + r - 2, gc = bx + c - 2;
        float v = BIG;
        if ((unsigned)gr < 512u && (unsigned)gc < 512u) {
            int rr = r + 1, cc = c + 1;
            float ce = s_img[rr * 71 + cc];
            v = fminf(ce, fminf(fminf(s_img[(rr - 1) * 71 + cc], s_img[(rr + 1) * 71 + cc]),
                                fminf(s_img[rr * 71 + cc - 1], s_img[rr * 71 + cc + 1])));
        }
        s_e1[r * 69 + c] = v;
    }
    __syncthreads();

    // E2 = erode(E1) on T+1; out-of-image -> -BIG (feeds dilate).
    // Stored into s_img (pitch 67) — s_img contents no longer needed.
    for (int i = tid; i < 66 * 66; i += NT) {
        int r = i / 66, c = i - r * 66;
        int gr = by + r - 1, gc = bx + c - 1;
        float v = -BIG;
        if ((unsigned)gr < 512u && (unsigned)gc < 512u) {
            int rr = r + 1, cc = c + 1;
            float ce = s_e1[rr * 69 + cc];
            v = fminf(ce, fminf(fminf(s_e1[(rr - 1) * 69 + cc], s_e1[(rr + 1) * 69 + cc]),
                                fminf(s_e1[rr * 69 + cc - 1], s_e1[rr * 69 + cc + 1])));
        }
        s_img[r * 67 + c] = v;
    }
    __syncthreads();

    // open = dilate(E2); delta; skel update; write img' = E1(center)
    for (int i = tid; i < TS * TS; i += NT) {
        int r = i >> 6, c = i & 63;
        float m = -BIG;
        #pragma unroll
        for (int dr = 0; dr < 3; dr++)
            #pragma unroll
            for (int dc = 0; dc < 3; dc++)
                m = fmaxf(m, s_img[(r + dr) * 67 + c + dc]);
        float e1c = s_e1[(r + 2) * 69 + (c + 2)];
        float delta = gelu_exact(e1c - m);
        int g = plane * PLANE + (by + r) * W + (bx + c);
        float sk = g_skel[g];
        sk += gelu_exact(delta - sk * delta);
        g_skel[g] = sk;
        dst[g] = e1c;
    }
}

// ---------------------------------------------------------------------------
// Reductions (deterministic two-stage tree)
// ---------------------------------------------------------------------------
__device__ __forceinline__ float warpSum(float v) {
    #pragma unroll
    for (int o = 16; o; o >>= 1) v += __shfl_down_sync(0xffffffffu, v, o);
    return v;
}

__global__ __launch_bounds__(256) void reduce_kernel(const float* __restrict__ yt,
                                                     const float* __restrict__ yp) {
    float a[7] = {0.f, 0.f, 0.f, 0.f, 0.f, 0.f, 0.f};
    const int stride = gridDim.x * blockDim.x;
    for (int i = blockIdx.x * blockDim.x + threadIdx.x; i < IMG_ELEMS; i += stride) {
        float t = yt[i], p = yp[i];
        float sp = g_skel[i];               // skel_pred (planes 0..15)
        float st = g_skel[i + IMG_ELEMS];   // skel_true (planes 16..31)
        a[0] += t;       a[1] += p;       a[2] += t * p;
        a[3] += sp;      a[4] += sp * t;
        a[5] += st;      a[6] += st * p;
    }
    __shared__ float shm[8][8];
    const int lane = threadIdx.x & 31, wrp = threadIdx.x >> 5;
    #pragma unroll
    for (int j = 0; j < 7; j++) {
        float v = warpSum(a[j]);
        if (lane == 0) shm[wrp][j] = v;
    }
    __syncthreads();
    if (wrp == 0) {
        #pragma unroll
        for (int j = 0; j < 7; j++) {
            float v = (lane < 8) ? shm[lane][j] : 0.f;
            v = warpSum(v);
            if (lane == 0) g_part[blockIdx.x * 8 + j] = v;
        }
    }
}

__global__ __launch_bounds__(256) void final_kernel(float* __restrict__ out) {
    float a[7] = {0.f, 0.f, 0.f, 0.f, 0.f, 0.f, 0.f};
    for (int b = threadIdx.x; b < RED_BLOCKS; b += 256) {
        #pragma unroll
        for (int j = 0; j < 7; j++) a[j] += g_part[b * 8 + j];
    }
    __shared__ float shm[8][8];
    const int lane = threadIdx.x & 31, wrp = threadIdx.x >> 5;
    #pragma unroll
    for (int j = 0; j < 7; j++) {
        float v = warpSum(a[j]);
        if (lane == 0) shm[wrp][j] = v;
    }
    __syncthreads();
    if (wrp == 0) {
        float res[7];
        #pragma unroll
        for (int j = 0; j < 7; j++) {
            float v = (lane < 8) ? shm[lane][j] : 0.f;
            res[j] = warpSum(v);
        }
        if (lane == 0) {
            float S_t  = res[0];  // sum(y_true)
            float S_p  = res[1];  // sum(y_pred)
            float S_tp = res[2];  // sum(y_true*y_pred)
            float S_sp = res[3];  // sum(skel_pred)
            float S_spt= res[4];  // sum(skel_pred*y_true)
            float S_st = res[5];  // sum(skel_true)
            float S_stp= res[6];  // sum(skel_true*y_pred)
            float dice  = 1.0f - (2.0f * S_tp + 1.0f) / (S_t + S_p + 1.0f);
            float tprec = (S_spt + 1.0f) / (S_sp + 1.0f);
            float tsens = (S_stp + 1.0f) / (S_st + 1.0f);
            float cl    = 1.0f - 2.0f * (tprec * tsens) / (tprec + tsens);
            out[0] = 0.7f * dice + 0.3f * cl;
        }
    }
}

// ---------------------------------------------------------------------------
extern "C" void kernel_launch(void* const* d_in, const int* in_sizes, int n_in,
                              void* d_out, int out_size) {
    const float* y_true = (const float*)d_in[0];
    const float* y_pred = (const float*)d_in[1];

    dim3 grid(W / TS, W / TS, NPLANES);  // 8 x 8 x 32 = 2048 blocks
    dim3 blk(NT);

    init_kernel<<<grid, blk>>>(y_true, y_pred);
    for (int s = 0; s < N_ITER; ++s)
        step_kernel<<<grid, blk>>>((s & 1) == 0 ? 1 : 0);

    reduce_kernel<<<RED_BLOCKS, 256>>>(y_true, y_pred);
    final_kernel<<<1, 256>>>((float*)d_out);
}

// round 5
// speedup vs baseline: 1.2050x; 1.2050x over previous
#include <cuda_runtime.h>

#define W 512
#define PLANE (512*512)
#define NPLANES 32
#define HALF 16
#define TOTAL (NPLANES*PLANE)
#define IMG_ELEMS (HALF*PLANE)
#define GP 520                  // padded pitch (4 + 512 + 4)
#define GR 518                  // padded rows  (3 + 512 + 3)
#define PSZ (GP*GR)
#define BOFF (3*GP + 4)         // offset of pixel (0,0) in a padded plane
#define NT 256
#define N_ITER 20
#define NBLOCKS 2048
#define BIGF 1e30f

// Scratch (device globals; no allocation allowed)
__device__ __align__(16) float g_bufA[NPLANES * PSZ];
__device__ __align__(16) float g_bufB[NPLANES * PSZ];
__device__ float g_skel[TOTAL];
__device__ float g_part[NBLOCKS * 8];

__device__ __forceinline__ float gelu_exact(float x) {
    return 0.5f * x * (1.0f + erff(x * 0.70710678118654752f));
}

// ---------------------------------------------------------------------------
// Fill both padded buffers with +BIG (provides +inf padding for erode loads).
// ---------------------------------------------------------------------------
__global__ __launch_bounds__(256) void fill_kernel() {
    const int n4 = (NPLANES * PSZ) / 4;
    const float4 v = make_float4(BIGF, BIGF, BIGF, BIGF);
    for (int i = blockIdx.x * blockDim.x + threadIdx.x; i < n4;
         i += gridDim.x * blockDim.x) {
        reinterpret_cast<float4*>(g_bufA)[i] = v;
        reinterpret_cast<float4*>(g_bufB)[i] = v;
    }
}

// ---------------------------------------------------------------------------
// INIT: skel = gelu(img - dilate(erode(img))); padded bufA = img
// smem: s_img 68x68 (pitch 70), s_e1 66x66 (pitch 68)
// ---------------------------------------------------------------------------
template<bool BORDER>
__device__ __forceinline__ void init_body(const float* __restrict__ src,
                                          float* s_img, float* s_e1,
                                          int plane, int by, int bx,
                                          int tx, int ty) {
    const int tid = ty * 64 + tx;

    // Load img with halo 2 (erode pads +BIG)
    for (int r = ty; r < 68; r += 4) {
        float* srow = s_img + r * 70;
        const int gr = by + r - 2;
        {
            const int gc = bx + tx - 2;
            float v;
            if (!BORDER) v = src[gr * W + gc];
            else v = ((unsigned)gr < 512u && (unsigned)gc < 512u) ? src[gr * W + gc] : BIGF;
            srow[tx] = v;
        }
        if (tx < 4) {
            const int gc = bx + tx + 62;
            float v;
            if (!BORDER) v = src[gr * W + gc];
            else v = ((unsigned)gr < 512u && (unsigned)gc < 512u) ? src[gr * W + gc] : BIGF;
            srow[tx + 64] = v;
        }
    }
    __syncthreads();

    // E1 = erode(img) on 66x66 (offset (-1,-1)); out-of-image -> -BIG (feeds dilate)
    {
        const int r0 = ty * 17;
        int r1 = r0 + 17; if (r1 > 66) r1 = 66;
        const int j = tx;
        float a = s_img[r0 * 70 + j + 1];
        float b = s_img[(r0 + 1) * 70 + j + 1];
        for (int i = r0; i < r1; ++i) {
            const float cn = s_img[(i + 2) * 70 + j + 1];
            float v = fminf(fminf(a, b), cn);
            v = fminf(v, fminf(s_img[(i + 1) * 70 + j], s_img[(i + 1) * 70 + j + 2]));
            if (BORDER) {
                const int gr = by + i - 1, gc = bx + j - 1;
                if ((unsigned)gr >= 512u || (unsigned)gc >= 512u) v = -BIGF;
            }
            s_e1[i * 68 + j] = v;
            a = b; b = cn;
        }
        // extra cols 64,65 (132 scattered elements)
        for (int e = tid; e < 132; e += NT) {
            const int q = e / 66, jj = 64 + q, i = e - q * 66;
            float v = fminf(fminf(s_img[i * 70 + jj + 1], s_img[(i + 1) * 70 + jj + 1]),
                            s_img[(i + 2) * 70 + jj + 1]);
            v = fminf(v, fminf(s_img[(i + 1) * 70 + jj], s_img[(i + 1) * 70 + jj + 2]));
            if (BORDER) {
                const int gr = by + i - 1, gc = bx + jj - 1;
                if ((unsigned)gr >= 512u || (unsigned)gc >= 512u) v = -BIGF;
            }
            s_e1[i * 68 + jj] = v;
        }
    }
    __syncthreads();

    // open = dilate(E1); skel = gelu(img - open); store img to padded bufA
    {
        const int r0 = ty * 16;
        const int c = tx;
        float x0 = s_e1[r0 * 68 + c], x1 = s_e1[r0 * 68 + c + 1], x2 = s_e1[r0 * 68 + c + 2];
        float rma = fmaxf(fmaxf(x0, x1), x2);
        x0 = s_e1[(r0 + 1) * 68 + c]; x1 = s_e1[(r0 + 1) * 68 + c + 1]; x2 = s_e1[(r0 + 1) * 68 + c + 2];
        float rmb = fmaxf(fmaxf(x0, x1), x2);
        float* dA = g_bufA + plane * PSZ + BOFF;
        for (int r = r0; r < r0 + 16; ++r) {
            x0 = s_e1[(r + 2) * 68 + c]; x1 = s_e1[(r + 2) * 68 + c + 1]; x2 = s_e1[(r + 2) * 68 + c + 2];
            const float rmc = fmaxf(fmaxf(x0, x1), x2);
            const float open_ = fmaxf(fmaxf(rma, rmb), rmc);
            const float img = s_img[(r + 2) * 70 + c + 2];
            const int g = plane * PLANE + (by + r) * W + (bx + c);
            g_skel[g] = gelu_exact(img - open_);
            dA[(by + r) * GP + (bx + c)] = img;
            rma = rmb; rmb = rmc;
        }
    }
}

__global__ __launch_bounds__(NT) void init_kernel(const float* __restrict__ yt,
                                                  const float* __restrict__ yp) {
    __shared__ float s_img[70 * 70];
    __shared__ float s_e1[68 * 68];
    const int plane = blockIdx.z;
    const float* src = ((plane < HALF) ? yp : yt) + (plane & 15) * PLANE;
    const int by = blockIdx.y * 64, bx = blockIdx.x * 64;
    const bool border = (blockIdx.x == 0) | (blockIdx.x == 7) | (blockIdx.y == 0) | (blockIdx.y == 7);
    if (border) init_body<true >(src, s_img, s_e1, plane, by, bx, threadIdx.x, threadIdx.y);
    else        init_body<false>(src, s_img, s_e1, plane, by, bx, threadIdx.x, threadIdx.y);
}

// ---------------------------------------------------------------------------
// STEP: img' = erode(img); delta = gelu(img' - dilate(erode(img')));
//       skel += gelu(delta - skel*delta)
// smem: s_img 70x70 (pitch 70; later aliased as E2 66x66 pitch 66),
//       s_e1 68x68 (pitch 68)
// RED: last step — fused 7-sum block reduction instead of skel store.
// ---------------------------------------------------------------------------
__device__ __forceinline__ float warpSum(float v) {
    #pragma unroll
    for (int o = 16; o; o >>= 1) v += __shfl_down_sync(0xffffffffu, v, o);
    return v;
}

template<bool BORDER, bool RED>
__device__ __forceinline__ void step_body(const float* __restrict__ sp,
                                          float* __restrict__ dp,
                                          const float* __restrict__ yt,
                                          const float* __restrict__ yp,
                                          float* s_img, float* s_e1, float* s_red,
                                          int plane, int by, int bx,
                                          int tx, int ty) {
    const int tid = ty * 64 + tx;
    float* s_e2 = s_img;   // alias: img dead after E1 pass

    // Load img with halo 3 from padded global (no predicates ever)
    {
        const float* g0 = sp + (by - 3) * GP + (bx - 3);
        for (int r = ty; r < 70; r += 4) {
            const float* grp = g0 + r * GP;
            float* srow = s_img + r * 70;
            srow[tx] = grp[tx];
            if (tx < 6) srow[tx + 64] = grp[tx + 64];
        }
    }
    __syncthreads();

    // E1 = erode(img) on 68x68 (offset (-2,-2)); out-of-image -> +BIG
    {
        const int r0 = ty * 17;
        const int j = tx;
        float a = s_img[r0 * 70 + j + 1];
        float b = s_img[(r0 + 1) * 70 + j + 1];
        for (int i = r0; i < r0 + 17; ++i) {
            const float cn = s_img[(i + 2) * 70 + j + 1];
            float v = fminf(fminf(a, b), cn);
            v = fminf(v, fminf(s_img[(i + 1) * 70 + j], s_img[(i + 1) * 70 + j + 2]));
            if (BORDER) {
                const int gr = by + i - 2, gc = bx + j - 2;
                if ((unsigned)gr >= 512u || (unsigned)gc >= 512u) v = BIGF;
            }
            s_e1[i * 68 + j] = v;
            a = b; b = cn;
        }
        for (int e = tid; e < 272; e += NT) {   // extra cols 64..67
            const int q = e / 68, jj = 64 + q, i = e - q * 68;
            float v = fminf(fminf(s_img[i * 70 + jj + 1], s_img[(i + 1) * 70 + jj + 1]),
                            s_img[(i + 2) * 70 + jj + 1]);
            v = fminf(v, fminf(s_img[(i + 1) * 70 + jj], s_img[(i + 1) * 70 + jj + 2]));
            if (BORDER) {
                const int gr = by + i - 2, gc = bx + jj - 2;
                if ((unsigned)gr >= 512u || (unsigned)gc >= 512u) v = BIGF;
            }
            s_e1[i * 68 + jj] = v;
        }
    }
    __syncthreads();

    // E2 = erode(E1) on 66x66 (offset (-1,-1)) into s_e2; out-of-image -> -BIG
    {
        const int r0 = ty * 17;
        int r1 = r0 + 17; if (r1 > 66) r1 = 66;
        const int j = tx;
        float a = s_e1[r0 * 68 + j + 1];
        float b = s_e1[(r0 + 1) * 68 + j + 1];
        for (int i = r0; i < r1; ++i) {
            const float cn = s_e1[(i + 2) * 68 + j + 1];
            float v = fminf(fminf(a, b), cn);
            v = fminf(v, fminf(s_e1[(i + 1) * 68 + j], s_e1[(i + 1) * 68 + j + 2]));
            if (BORDER) {
                const int gr = by + i - 1, gc = bx + j - 1;
                if ((unsigned)gr >= 512u || (unsigned)gc >= 512u) v = -BIGF;
            }
            s_e2[i * 66 + j] = v;
            a = b; b = cn;
        }
        for (int e = tid; e < 132; e += NT) {   // extra cols 64,65
            const int q = e / 66, jj = 64 + q, i = e - q * 66;
            float v = fminf(fminf(s_e1[i * 68 + jj + 1], s_e1[(i + 1) * 68 + jj + 1]),
                            s_e1[(i + 2) * 68 + jj + 1]);
            v = fminf(v, fminf(s_e1[(i + 1) * 68 + jj], s_e1[(i + 1) * 68 + jj + 2]));
            if (BORDER) {
                const int gr = by + i - 1, gc = bx + jj - 1;
                if ((unsigned)gr >= 512u || (unsigned)gc >= 512u) v = -BIGF;
            }
            s_e2[i * 66 + jj] = v;
        }
    }
    __syncthreads();

    // open = dilate(E2) (rolling row-maxes); delta; skel update; write img'=E1
    {
        float a0 = 0.f, a1 = 0.f, a2 = 0.f, a3 = 0.f, a4 = 0.f, a5 = 0.f, a6 = 0.f;
        const int r0 = ty * 16;
        const int c = tx;
        float x0 = s_e2[r0 * 66 + c], x1 = s_e2[r0 * 66 + c + 1], x2 = s_e2[r0 * 66 + c + 2];
        float rma = fmaxf(fmaxf(x0, x1), x2);
        x0 = s_e2[(r0 + 1) * 66 + c]; x1 = s_e2[(r0 + 1) * 66 + c + 1]; x2 = s_e2[(r0 + 1) * 66 + c + 2];
        float rmb = fmaxf(fmaxf(x0, x1), x2);
        for (int r = r0; r < r0 + 16; ++r) {
            x0 = s_e2[(r + 2) * 66 + c]; x1 = s_e2[(r + 2) * 66 + c + 1]; x2 = s_e2[(r + 2) * 66 + c + 2];
            const float rmc = fmaxf(fmaxf(x0, x1), x2);
            const float open_ = fmaxf(fmaxf(rma, rmb), rmc);
            const float e1c = s_e1[(r + 2) * 68 + c + 2];
            const float delta = gelu_exact(e1c - open_);
            const int g = plane * PLANE + (by + r) * W + (bx + c);
            float sk = g_skel[g];
            sk += gelu_exact(delta - sk * delta);
            if (!RED) g_skel[g] = sk;
            dp[(by + r) * GP + (bx + c)] = e1c;
            if (RED) {
                const int gi = (plane & 15) * PLANE + (by + r) * W + (bx + c);
                if (plane < HALF) {
                    const float t = yt[gi], p = yp[gi];
                    a0 += t; a1 += p; a2 += t * p; a3 += sk; a4 += sk * t;
                } else {
                    const float p = yp[gi];
                    a5 += sk; a6 += sk * p;
                }
            }
            rma = rmb; rmb = rmc;
        }
        if (RED) {
            float v[7] = {a0, a1, a2, a3, a4, a5, a6};
            const int lane = tid & 31, wrp = tid >> 5;
            #pragma unroll
            for (int k = 0; k < 7; k++) {
                const float s = warpSum(v[k]);
                if (lane == 0) s_red[wrp * 8 + k] = s;
            }
            __syncthreads();
            if (wrp == 0) {
                const int bid = plane * 64 + (by >> 6) * 8 + (bx >> 6);
                #pragma unroll
                for (int k = 0; k < 7; k++) {
                    float s = (lane < 8) ? s_red[lane * 8 + k] : 0.f;
                    s = warpSum(s);
                    if (lane == 0) g_part[bid * 8 + k] = s;
                }
            }
        }
    }
}

__global__ __launch_bounds__(NT) void step_kernel(int readA) {
    __shared__ float s_img[70 * 70];
    __shared__ float s_e1[68 * 68];
    const float* src = readA ? g_bufA : g_bufB;
    float* dst = readA ? g_bufB : g_bufA;
    const int plane = blockIdx.z;
    const int by = blockIdx.y * 64, bx = blockIdx.x * 64;
    const float* sp = src + plane * PSZ + BOFF;
    float* dp = dst + plane * PSZ + BOFF;
    const bool border = (blockIdx.x == 0) | (blockIdx.x == 7) | (blockIdx.y == 0) | (blockIdx.y == 7);
    if (border) step_body<true , false>(sp, dp, nullptr, nullptr, s_img, s_e1, nullptr,
                                        plane, by, bx, threadIdx.x, threadIdx.y);
    else        step_body<false, false>(sp, dp, nullptr, nullptr, s_img, s_e1, nullptr,
                                        plane, by, bx, threadIdx.x, threadIdx.y);
}

__global__ __launch_bounds__(NT) void step_red_kernel(const float* __restrict__ yt,
                                                      const float* __restrict__ yp,
                                                      int readA) {
    __shared__ float s_img[70 * 70];
    __shared__ float s_e1[68 * 68];
    __shared__ float s_red[64];
    const float* src = readA ? g_bufA : g_bufB;
    float* dst = readA ? g_bufB : g_bufA;
    const int plane = blockIdx.z;
    const int by = blockIdx.y * 64, bx = blockIdx.x * 64;
    const float* sp = src + plane * PSZ + BOFF;
    float* dp = dst + plane * PSZ + BOFF;
    const bool border = (blockIdx.x == 0) | (blockIdx.x == 7) | (blockIdx.y == 0) | (blockIdx.y == 7);
    if (border) step_body<true , true>(sp, dp, yt, yp, s_img, s_e1, s_red,
                                       plane, by, bx, threadIdx.x, threadIdx.y);
    else        step_body<false, true>(sp, dp, yt, yp, s_img, s_e1, s_red,
                                       plane, by, bx, threadIdx.x, threadIdx.y);
}

// ---------------------------------------------------------------------------
// Final: sum 2048 partials, compute loss scalar
// ---------------------------------------------------------------------------
__global__ __launch_bounds__(256) void final_kernel(float* __restrict__ out) {
    float a[7] = {0.f, 0.f, 0.f, 0.f, 0.f, 0.f, 0.f};
    for (int b = threadIdx.x; b < NBLOCKS; b += 256) {
        #pragma unroll
        for (int j = 0; j < 7; j++) a[j] += g_part[b * 8 + j];
    }
    __shared__ float shm[8][8];
    const int lane = threadIdx.x & 31, wrp = threadIdx.x >> 5;
    #pragma unroll
    for (int j = 0; j < 7; j++) {
        const float v = warpSum(a[j]);
        if (lane == 0) shm[wrp][j] = v;
    }
    __syncthreads();
    if (wrp == 0) {
        float res[7];
        #pragma unroll
        for (int j = 0; j < 7; j++) {
            float v = (lane < 8) ? shm[lane][j] : 0.f;
            res[j] = warpSum(v);
        }
        if (lane == 0) {
            const float S_t = res[0], S_p = res[1], S_tp = res[2];
            const float S_sp = res[3], S_spt = res[4];
            const float S_st = res[5], S_stp = res[6];
            const float dice  = 1.0f - (2.0f * S_tp + 1.0f) / (S_t + S_p + 1.0f);
            const float tprec = (S_spt + 1.0f) / (S_sp + 1.0f);
            const float tsens = (S_stp + 1.0f) / (S_st + 1.0f);
            const float cl    = 1.0f - 2.0f * (tprec * tsens) / (tprec + tsens);
            out[0] = 0.7f * dice + 0.3f * cl;
        }
    }
}

// ---------------------------------------------------------------------------
extern "C" void kernel_launch(void* const* d_in, const int* in_sizes, int n_in,
                              void* d_out, int out_size) {
    const float* y_true = (const float*)d_in[0];
    const float* y_pred = (const float*)d_in[1];

    dim3 grid(8, 8, NPLANES);
    dim3 blk(64, 4);

    fill_kernel<<<1024, 256>>>();
    init_kernel<<<grid, blk>>>(y_true, y_pred);
    for (int s = 0; s < N_ITER - 1; ++s)
        step_kernel<<<grid, blk>>>((s & 1) == 0 ? 1 : 0);
    step_red_kernel<<<grid, blk>>>(y_true, y_pred, ((N_ITER - 1) & 1) == 0 ? 1 : 0);
    final_kernel<<<1, 256>>>((float*)d_out);
}

// round 7
// speedup vs baseline: 1.8150x; 1.5062x over previous
#include <cuda_runtime.h>

#define W 512
#define PLANE (512*512)
#define NPLANES 32
#define HALF 16
#define TOTAL (NPLANES*PLANE)
#define GP 524                  // padded pitch (6 + 512 + 6)
#define GR 524
#define PSZ (GP*GR)
#define BOFF (6*GP + 6)         // offset of pixel (0,0) in a padded plane
#define NT 256
#define NBLOCKS 2048
#define BIGF 1e30f

// Scratch (device globals; no allocation allowed)
__device__ __align__(16) float g_bufA[NPLANES * PSZ];
__device__ __align__(16) float g_bufB[NPLANES * PSZ];
__device__ float g_skel[TOTAL];
__device__ float g_part[NBLOCKS * 8];

__device__ __forceinline__ float gelu_exact(float x) {
    return 0.5f * x * (1.0f + erff(x * 0.70710678118654752f));
}

// ---------------------------------------------------------------------------
// Fill both padded buffers with +BIG (erode-friendly pad ring, written once).
// ---------------------------------------------------------------------------
__global__ __launch_bounds__(256) void fill_kernel() {
    const int n4 = (NPLANES * PSZ) / 4;
    const float4 v = make_float4(BIGF, BIGF, BIGF, BIGF);
    for (int i = blockIdx.x * blockDim.x + threadIdx.x; i < n4;
         i += gridDim.x * blockDim.x) {
        reinterpret_cast<float4*>(g_bufA)[i] = v;
        reinterpret_cast<float4*>(g_bufB)[i] = v;
    }
}

// ---------------------------------------------------------------------------
// INIT: skel = gelu(img - dilate(erode(img))); padded bufA = img
// ---------------------------------------------------------------------------
template<bool BORDER>
__device__ __forceinline__ void init_body(const float* __restrict__ src,
                                          float* s_img, float* s_e1,
                                          int plane, int by, int bx,
                                          int tx, int ty) {
    const int tid = ty * 64 + tx;

    for (int r = ty; r < 68; r += 4) {
        float* srow = s_img + r * 70;
        const int gr = by + r - 2;
        {
            const int gc = bx + tx - 2;
            float v;
            if (!BORDER) v = src[gr * W + gc];
            else v = ((unsigned)gr < 512u && (unsigned)gc < 512u) ? src[gr * W + gc] : BIGF;
            srow[tx] = v;
        }
        if (tx < 4) {
            const int gc = bx + tx + 62;
            float v;
            if (!BORDER) v = src[gr * W + gc];
            else v = ((unsigned)gr < 512u && (unsigned)gc < 512u) ? src[gr * W + gc] : BIGF;
            srow[tx + 64] = v;
        }
    }
    __syncthreads();

    // E1 = erode(img) on 66x66 (halo 1); out-of-image -> -BIG (feeds dilate only)
    {
        const int r0 = ty * 17;
        int r1 = r0 + 17; if (r1 > 66) r1 = 66;
        const int j = tx;
        float a = s_img[r0 * 70 + j + 1];
        float b = s_img[(r0 + 1) * 70 + j + 1];
        for (int i = r0; i < r1; ++i) {
            const float cn = s_img[(i + 2) * 70 + j + 1];
            float v = fminf(fminf(a, b), cn);
            v = fminf(v, fminf(s_img[(i + 1) * 70 + j], s_img[(i + 1) * 70 + j + 2]));
            if (BORDER) {
                const int gr = by + i - 1, gc = bx + j - 1;
                if ((unsigned)gr >= 512u || (unsigned)gc >= 512u) v = -BIGF;
            }
            s_e1[i * 68 + j] = v;
            a = b; b = cn;
        }
        for (int e = tid; e < 132; e += NT) {
            const int q = e / 66, jj = 64 + q, i = e - q * 66;
            float v = fminf(fminf(s_img[i * 70 + jj + 1], s_img[(i + 1) * 70 + jj + 1]),
                            s_img[(i + 2) * 70 + jj + 1]);
            v = fminf(v, fminf(s_img[(i + 1) * 70 + jj], s_img[(i + 1) * 70 + jj + 2]));
            if (BORDER) {
                const int gr = by + i - 1, gc = bx + jj - 1;
                if ((unsigned)gr >= 512u || (unsigned)gc >= 512u) v = -BIGF;
            }
            s_e1[i * 68 + jj] = v;
        }
    }
    __syncthreads();

    // open = dilate(E1); skel = gelu(img - open); store img to padded bufA
    {
        const int r0 = ty * 16;
        const int c = tx;
        float x0 = s_e1[r0 * 68 + c], x1 = s_e1[r0 * 68 + c + 1], x2 = s_e1[r0 * 68 + c + 2];
        float rma = fmaxf(fmaxf(x0, x1), x2);
        x0 = s_e1[(r0 + 1) * 68 + c]; x1 = s_e1[(r0 + 1) * 68 + c + 1]; x2 = s_e1[(r0 + 1) * 68 + c + 2];
        float rmb = fmaxf(fmaxf(x0, x1), x2);
        float* dA = g_bufA + plane * PSZ + BOFF;
        for (int r = r0; r < r0 + 16; ++r) {
            x0 = s_e1[(r + 2) * 68 + c]; x1 = s_e1[(r + 2) * 68 + c + 1]; x2 = s_e1[(r + 2) * 68 + c + 2];
            const float rmc = fmaxf(fmaxf(x0, x1), x2);
            const float open_ = fmaxf(fmaxf(rma, rmb), rmc);
            const float img = s_img[(r + 2) * 70 + c + 2];
            g_skel[plane * PLANE + (by + r) * W + (bx + c)] = gelu_exact(img - open_);
            dA[(by + r) * GP + (bx + c)] = img;
            rma = rmb; rmb = rmc;
        }
    }
}

__global__ __launch_bounds__(NT) void init_kernel(const float* __restrict__ yt,
                                                  const float* __restrict__ yp) {
    __shared__ float s_img[70 * 70];
    __shared__ float s_e1[68 * 68];
    const int plane = blockIdx.z;
    const float* src = ((plane < HALF) ? yp : yt) + (plane & 15) * PLANE;
    const int by = blockIdx.y * 64, bx = blockIdx.x * 64;
    const bool border = (blockIdx.x == 0) | (blockIdx.x == 7) | (blockIdx.y == 0) | (blockIdx.y == 7);
    if (border) init_body<true >(src, s_img, s_e1, plane, by, bx, threadIdx.x, threadIdx.y);
    else        init_body<false>(src, s_img, s_e1, plane, by, bx, threadIdx.x, threadIdx.y);
}

// ---------------------------------------------------------------------------
// Fused 4-step kernel building blocks
// ---------------------------------------------------------------------------
// Generic erode: in (DIN x DIN, halo HOUT+1) -> out (DIN-2 x DIN-2, halo HOUT).
// Out-of-image outputs get +BIG (erode-friendly); dilate consumers clamp.
template<int DIN, int HOUT, bool BORDER>
__device__ __forceinline__ void erode_pass(const float* __restrict__ in,
                                           float* __restrict__ out,
                                           int by, int bx, int tx, int ty, int tid) {
    constexpr int DOUT = DIN - 2;
    constexpr int RPT = (DOUT + 3) / 4;
    {
        const int j = tx;
        const int r0 = ty * RPT;
        int r1 = r0 + RPT; if (r1 > DOUT) r1 = DOUT;
        float a = in[r0 * DIN + j + 1];
        float b = in[(r0 + 1) * DIN + j + 1];
        for (int i = r0; i < r1; ++i) {
            const float cn = in[(i + 2) * DIN + j + 1];
            float v = fminf(fminf(a, b), cn);
            v = fminf(v, fminf(in[(i + 1) * DIN + j], in[(i + 1) * DIN + j + 2]));
            if (BORDER) {
                const int gr = by + i - HOUT, gc = bx + j - HOUT;
                if ((unsigned)gr >= 512u || (unsigned)gc >= 512u) v = BIGF;
            }
            out[i * DOUT + j] = v;
            a = b; b = cn;
        }
    }
    constexpr int EX = (DOUT - 64) * DOUT;
    for (int e = tid; e < EX; e += NT) {
        const int q = e / DOUT, jj = 64 + q, i = e - q * DOUT;
        float v = fminf(fminf(in[i * DIN + jj + 1], in[(i + 1) * DIN + jj + 1]),
                        in[(i + 2) * DIN + jj + 1]);
        v = fminf(v, fminf(in[(i + 1) * DIN + jj], in[(i + 1) * DIN + jj + 2]));
        if (BORDER) {
            const int gr = by + i - HOUT, gc = bx + jj - HOUT;
            if ((unsigned)gr >= 512u || (unsigned)gc >= 512u) v = BIGF;
        }
        out[i * DOUT + jj] = v;
    }
}

template<int DK1, bool BORDER>
__device__ __forceinline__ float rowmax3(const float* __restrict__ ek1, int ri, int cc,
                                         bool ok0, bool ok2, bool row_ok) {
    float v0 = ek1[ri * DK1 + cc - 1];
    float v1 = ek1[ri * DK1 + cc];
    float v2 = ek1[ri * DK1 + cc + 1];
    if (BORDER) { if (!ok0) v0 = -BIGF; if (!ok2) v2 = -BIGF; }
    float m = fmaxf(fmaxf(v0, v1), v2);
    if (BORDER) { if (!row_ok) m = -BIGF; }
    return m;
}

// Update: delta = gelu(Ek - dilate(Ek1)); sk += gelu(delta - sk*delta)
// Ek: DK x DK, halo HK. Ek1: (DK-2)x(DK-2), halo HK-1. skel in registers.
template<int DK, int HK, bool BORDER>
__device__ __forceinline__ void upd_pass(const float* __restrict__ ek,
                                         const float* __restrict__ ek1,
                                         float* sk, int by, int bx, int tx, int ty) {
    constexpr int DK1 = DK - 2, H1 = HK - 1;
    const int c = tx, r0 = ty * 16;
    const int cc = c + H1;
    bool ok0 = true, ok2 = true;
    if (BORDER) {
        ok0 = (unsigned)(bx + c - 1) < 512u;
        ok2 = (unsigned)(bx + c + 1) < 512u;
    }
    float rma = rowmax3<DK1, BORDER>(ek1, r0 + H1 - 1, cc, ok0, ok2,
                                     (unsigned)(by + r0 - 1) < 512u);
    float rmb = rowmax3<DK1, BORDER>(ek1, r0 + H1, cc, ok0, ok2, true);
    #pragma unroll
    for (int q = 0; q < 16; ++q) {
        const int r = r0 + q;
        const float rmc = rowmax3<DK1, BORDER>(ek1, r + H1 + 1, cc, ok0, ok2,
                                               (unsigned)(by + r + 1) < 512u);
        const float open_ = fmaxf(fmaxf(rma, rmb), rmc);
        const float ekc = ek[(r + HK) * DK + c + HK];
        const float delta = gelu_exact(ekc - open_);
        float s = sk[q];
        s += gelu_exact(delta - s * delta);
        sk[q] = s;
        rma = rmb; rmb = rmc;
    }
}

__device__ __forceinline__ float warpSum(float v) {
    #pragma unroll
    for (int o = 16; o; o >>= 1) v += __shfl_down_sync(0xffffffffu, v, o);
    return v;
}

// 4 fused soft-skel iterations. x (halo 6) -> E1..E5; skel in 16 registers.
template<bool BORDER, bool RED>
__device__ __forceinline__ void fused_body(const float* __restrict__ sp,
                                           float* __restrict__ dp,
                                           const float* __restrict__ yt,
                                           const float* __restrict__ yp,
                                           float* sX, float* sY, float* s_red,
                                           int plane, int by, int bx,
                                           int tx, int ty) {
    const int tid = ty * 64 + tx;

    // Load x with halo 6 from padded global — zero predicates.
    {
        const float* g0 = sp + (by - 6) * GP + (bx - 6);
        for (int r = ty; r < 76; r += 4) {
            const float* grp = g0 + r * GP;
            float* srow = sX + r * 76;
            srow[tx] = grp[tx];
            if (tx < 12) srow[tx + 64] = grp[tx + 64];
        }
    }
    __syncthreads();

    erode_pass<76, 5, BORDER>(sX, sY, by, bx, tx, ty, tid);   // E1 (74, h5)
    __syncthreads();
    erode_pass<74, 4, BORDER>(sY, sX, by, bx, tx, ty, tid);   // E2 (72, h4)
    __syncthreads();

    float sk[16];
    const int r0 = ty * 16, c = tx;
    {
        const float* gs = &g_skel[plane * PLANE + (by + r0) * W + bx + c];
        #pragma unroll
        for (int q = 0; q < 16; ++q) sk[q] = gs[q * W];
    }
    upd_pass<74, 5, BORDER>(sY, sX, sk, by, bx, tx, ty);      // step 1
    __syncthreads();
    erode_pass<72, 3, BORDER>(sX, sY, by, bx, tx, ty, tid);   // E3 (70, h3)
    __syncthreads();
    upd_pass<72, 4, BORDER>(sX, sY, sk, by, bx, tx, ty);      // step 2
    __syncthreads();
    erode_pass<70, 2, BORDER>(sY, sX, by, bx, tx, ty, tid);   // E4 (68, h2)
    __syncthreads();
    upd_pass<70, 3, BORDER>(sY, sX, sk, by, bx, tx, ty);      // step 3
    __syncthreads();
    erode_pass<68, 1, BORDER>(sX, sY, by, bx, tx, ty, tid);   // E5 (66, h1)
    __syncthreads();
    upd_pass<68, 2, BORDER>(sX, sY, sk, by, bx, tx, ty);      // step 4

    if (!RED) {
        float* gs = &g_skel[plane * PLANE + (by + r0) * W + bx + c];
        float* gd = dp + (by + r0) * GP + bx + c;
        #pragma unroll
        for (int q = 0; q < 16; ++q) {
            gs[q * W] = sk[q];
            gd[q * GP] = sX[(r0 + q + 2) * 68 + c + 2];   // new img = E4 center
        }
    } else {
        float a0 = 0.f, a1 = 0.f, a2 = 0.f, a3 = 0.f, a4 = 0.f, a5 = 0.f, a6 = 0.f;
        const int gi0 = (plane & 15) * PLANE + (by + r0) * W + bx + c;
        if (plane < HALF) {
            #pragma unroll
            for (int q = 0; q < 16; ++q) {
                const float t = yt[gi0 + q * W], p = yp[gi0 + q * W], s = sk[q];
                a0 += t; a1 += p; a2 += t * p; a3 += s; a4 += s * t;
            }
        } else {
            #pragma unroll
            for (int q = 0; q < 16; ++q) {
                const float p = yp[gi0 + q * W], s = sk[q];
                a5 += s; a6 += s * p;
            }
        }
        float v[7] = {a0, a1, a2, a3, a4, a5, a6};
        const int lane = tid & 31, wrp = tid >> 5;
        #pragma unroll
        for (int k = 0; k < 7; k++) {
            const float s = warpSum(v[k]);
            if (lane == 0) s_red[wrp * 8 + k] = s;
        }
        __syncthreads();
        if (wrp == 0) {
            const int bid = plane * 64 + (by >> 6) * 8 + (bx >> 6);
            #pragma unroll
            for (int k = 0; k < 7; k++) {
                float s = (lane < 8) ? s_red[lane * 8 + k] : 0.f;
                s = warpSum(s);
                if (lane == 0) g_part[bid * 8 + k] = s;
            }
        }
    }
}

__global__ __launch_bounds__(NT) void fused_kernel(int readA) {
    __shared__ float sX[76 * 76];
    __shared__ float sY[74 * 74];
    const float* src = readA ? g_bufA : g_bufB;
    float* dst = readA ? g_bufB : g_bufA;
    const int plane = blockIdx.z;
    const int by = blockIdx.y * 64, bx = blockIdx.x * 64;
    const float* sp = src + plane * PSZ + BOFF;
    float* dp = dst + plane * PSZ + BOFF;
    const bool border = (blockIdx.x == 0) | (blockIdx.x == 7) | (blockIdx.y == 0) | (blockIdx.y == 7);
    if (border) fused_body<true , false>(sp, dp, nullptr, nullptr, sX, sY, nullptr,
                                         plane, by, bx, threadIdx.x, threadIdx.y);
    else        fused_body<false, false>(sp, dp, nullptr, nullptr, sX, sY, nullptr,
                                         plane, by, bx, threadIdx.x, threadIdx.y);
}

__global__ __launch_bounds__(NT) void fused_red_kernel(const float* __restrict__ yt,
                                                       const float* __restrict__ yp,
                                                       int readA) {
    __shared__ float sX[76 * 76];
    __shared__ float sY[74 * 74];
    __shared__ float s_red[64];
    const float* src = readA ? g_bufA : g_bufB;
    float* dst = readA ? g_bufB : g_bufA;
    const int plane = blockIdx.z;
    const int by = blockIdx.y * 64, bx = blockIdx.x * 64;
    const float* sp = src + plane * PSZ + BOFF;
    float* dp = dst + plane * PSZ + BOFF;
    const bool border = (blockIdx.x == 0) | (blockIdx.x == 7) | (blockIdx.y == 0) | (blockIdx.y == 7);
    if (border) fused_body<true , true>(sp, dp, yt, yp, sX, sY, s_red,
                                        plane, by, bx, threadIdx.x, threadIdx.y);
    else        fused_body<false, true>(sp, dp, yt, yp, sX, sY, s_red,
                                        plane, by, bx, threadIdx.x, threadIdx.y);
}

// ---------------------------------------------------------------------------
// Final: sum 2048 partials, compute loss scalar
// ---------------------------------------------------------------------------
__global__ __launch_bounds__(256) void final_kernel(float* __restrict__ out) {
    float a[7] = {0.f, 0.f, 0.f, 0.f, 0.f, 0.f, 0.f};
    for (int b = threadIdx.x; b < NBLOCKS; b += 256) {
        #pragma unroll
        for (int j = 0; j < 7; j++) a[j] += g_part[b * 8 + j];
    }
    __shared__ float shm[8][8];
    const int lane = threadIdx.x & 31, wrp = threadIdx.x >> 5;
    #pragma unroll
    for (int j = 0; j < 7; j++) {
        const float v = warpSum(a[j]);
        if (lane == 0) shm[wrp][j] = v;
    }
    __syncthreads();
    if (wrp == 0) {
        float res[7];
        #pragma unroll
        for (int j = 0; j < 7; j++) {
            float v = (lane < 8) ? shm[lane][j] : 0.f;
            res[j] = warpSum(v);
        }
        if (lane == 0) {
            const float S_t = res[0], S_p = res[1], S_tp = res[2];
            const float S_sp = res[3], S_spt = res[4];
            const float S_st = res[5], S_stp = res[6];
            const float dice  = 1.0f - (2.0f * S_tp + 1.0f) / (S_t + S_p + 1.0f);
            const float tprec = (S_spt + 1.0f) / (S_sp + 1.0f);
            const float tsens = (S_stp + 1.0f) / (S_st + 1.0f);
            const float cl    = 1.0f - 2.0f * (tprec * tsens) / (tprec + tsens);
            out[0] = 0.7f * dice + 0.3f * cl;
        }
    }
}

// ---------------------------------------------------------------------------
extern "C" void kernel_launch(void* const* d_in, const int* in_sizes, int n_in,
                              void* d_out, int out_size) {
    const float* y_true = (const float*)d_in[0];
    const float* y_pred = (const float*)d_in[1];

    dim3 grid(8, 8, NPLANES);
    dim3 blk(64, 4);

    fill_kernel<<<1024, 256>>>();
    init_kernel<<<grid, blk>>>(y_true, y_pred);
    fused_kernel<<<grid, blk>>>(1);      // steps 1-4   A -> B
    fused_kernel<<<grid, blk>>>(0);      // steps 5-8   B -> A
    fused_kernel<<<grid, blk>>>(1);      // steps 9-12  A -> B
    fused_kernel<<<grid, blk>>>(0);      // steps 13-16 B -> A
    fused_red_kernel<<<grid, blk>>>(y_true, y_pred, 1);  // steps 17-20 + sums
    final_kernel<<<1, 256>>>((float*)d_out);
}

// round 9
// speedup vs baseline: 2.0895x; 1.1512x over previous
#include <cuda_runtime.h>

#define W 512
#define PLANE (512*512)
#define NPLANES 32
#define HALF 16
#define TOTAL (NPLANES*PLANE)
#define GP 524                  // padded pitch (6 + 512 + 6)
#define GR 524
#define PSZ (GP*GR)
#define BOFF (6*GP + 6)         // offset of pixel (0,0) in a padded plane
#define NT 256
#define NBLOCKS 2048
#define BIGF 1e30f

// Scratch (device globals; no allocation allowed)
__device__ __align__(16) float g_bufA[NPLANES * PSZ];
__device__ __align__(16) float g_bufB[NPLANES * PSZ];
__device__ __align__(16) float g_skel[TOTAL];
__device__ float g_part[NBLOCKS * 8];

__device__ __forceinline__ float gelu_exact(float x) {
    return 0.5f * x * (1.0f + erff(x * 0.70710678118654752f));
}

// ---------------------------------------------------------------------------
// Fill both padded buffers with +BIG (erode-friendly pad ring, written once).
// ---------------------------------------------------------------------------
__global__ __launch_bounds__(256) void fill_kernel() {
    const int n4 = (NPLANES * PSZ) / 4;
    const float4 v = make_float4(BIGF, BIGF, BIGF, BIGF);
    for (int i = blockIdx.x * blockDim.x + threadIdx.x; i < n4;
         i += gridDim.x * blockDim.x) {
        reinterpret_cast<float4*>(g_bufA)[i] = v;
        reinterpret_cast<float4*>(g_bufB)[i] = v;
    }
}

// ---------------------------------------------------------------------------
// INIT: skel = gelu(img - dilate(erode(img))); padded bufA = img
// (launched with block (64,4) — one-shot kernel, kept scalar)
// ---------------------------------------------------------------------------
template<bool BORDER>
__device__ __forceinline__ void init_body(const float* __restrict__ src,
                                          float* s_img, float* s_e1,
                                          int plane, int by, int bx,
                                          int tx, int ty) {
    const int tid = ty * 64 + tx;

    for (int r = ty; r < 68; r += 4) {
        float* srow = s_img + r * 70;
        const int gr = by + r - 2;
        {
            const int gc = bx + tx - 2;
            float v;
            if (!BORDER) v = src[gr * W + gc];
            else v = ((unsigned)gr < 512u && (unsigned)gc < 512u) ? src[gr * W + gc] : BIGF;
            srow[tx] = v;
        }
        if (tx < 4) {
            const int gc = bx + tx + 62;
            float v;
            if (!BORDER) v = src[gr * W + gc];
            else v = ((unsigned)gr < 512u && (unsigned)gc < 512u) ? src[gr * W + gc] : BIGF;
            srow[tx + 64] = v;
        }
    }
    __syncthreads();

    // E1 = erode(img) on 66x66 (halo 1); out-of-image -> -BIG (feeds dilate only)
    {
        const int r0 = ty * 17;
        int r1 = r0 + 17; if (r1 > 66) r1 = 66;
        const int j = tx;
        float a = s_img[r0 * 70 + j + 1];
        float b = s_img[(r0 + 1) * 70 + j + 1];
        for (int i = r0; i < r1; ++i) {
            const float cn = s_img[(i + 2) * 70 + j + 1];
            float v = fminf(fminf(a, b), cn);
            v = fminf(v, fminf(s_img[(i + 1) * 70 + j], s_img[(i + 1) * 70 + j + 2]));
            if (BORDER) {
                const int gr = by + i - 1, gc = bx + j - 1;
                if ((unsigned)gr >= 512u || (unsigned)gc >= 512u) v = -BIGF;
            }
            s_e1[i * 68 + j] = v;
            a = b; b = cn;
        }
        for (int e = tid; e < 132; e += NT) {
            const int q = e / 66, jj = 64 + q, i = e - q * 66;
            float v = fminf(fminf(s_img[i * 70 + jj + 1], s_img[(i + 1) * 70 + jj + 1]),
                            s_img[(i + 2) * 70 + jj + 1]);
            v = fminf(v, fminf(s_img[(i + 1) * 70 + jj], s_img[(i + 1) * 70 + jj + 2]));
            if (BORDER) {
                const int gr = by + i - 1, gc = bx + jj - 1;
                if ((unsigned)gr >= 512u || (unsigned)gc >= 512u) v = -BIGF;
            }
            s_e1[i * 68 + jj] = v;
        }
    }
    __syncthreads();

    // open = dilate(E1); skel = gelu(img - open); store img to padded bufA
    {
        const int r0 = ty * 16;
        const int c = tx;
        float x0 = s_e1[r0 * 68 + c], x1 = s_e1[r0 * 68 + c + 1], x2 = s_e1[r0 * 68 + c + 2];
        float rma = fmaxf(fmaxf(x0, x1), x2);
        x0 = s_e1[(r0 + 1) * 68 + c]; x1 = s_e1[(r0 + 1) * 68 + c + 1]; x2 = s_e1[(r0 + 1) * 68 + c + 2];
        float rmb = fmaxf(fmaxf(x0, x1), x2);
        float* dA = g_bufA + plane * PSZ + BOFF;
        for (int r = r0; r < r0 + 16; ++r) {
            x0 = s_e1[(r + 2) * 68 + c]; x1 = s_e1[(r + 2) * 68 + c + 1]; x2 = s_e1[(r + 2) * 68 + c + 2];
            const float rmc = fmaxf(fmaxf(x0, x1), x2);
            const float open_ = fmaxf(fmaxf(rma, rmb), rmc);
            const float img = s_img[(r + 2) * 70 + c + 2];
            g_skel[plane * PLANE + (by + r) * W + (bx + c)] = gelu_exact(img - open_);
            dA[(by + r) * GP + (bx + c)] = img;
            rma = rmb; rmb = rmc;
        }
    }
}

__global__ __launch_bounds__(NT) void init_kernel(const float* __restrict__ yt,
                                                  const float* __restrict__ yp) {
    __shared__ __align__(16) float s_img[70 * 70];
    __shared__ __align__(16) float s_e1[68 * 68];
    const int plane = blockIdx.z;
    const float* src = ((plane < HALF) ? yp : yt) + (plane & 15) * PLANE;
    const int by = blockIdx.y * 64, bx = blockIdx.x * 64;
    const bool border = (blockIdx.x == 0) | (blockIdx.x == 7) | (blockIdx.y == 0) | (blockIdx.y == 7);
    if (border) init_body<true >(src, s_img, s_e1, plane, by, bx, threadIdx.x, threadIdx.y);
    else        init_body<false>(src, s_img, s_e1, plane, by, bx, threadIdx.x, threadIdx.y);
}

// ---------------------------------------------------------------------------
// Fused 4-step kernel building blocks — pairwise (float2), block (32,8).
// ---------------------------------------------------------------------------
// erode: in (DIN x DIN, halo HOUT+1) -> out (DIN-2 x DIN-2, halo HOUT).
// Each thread: output columns (2tx, 2tx+1), rolling 4-wide register window.
template<int DIN, int HOUT, bool BORDER>
__device__ __forceinline__ void erode_pair(const float* __restrict__ in,
                                           float* __restrict__ out,
                                           int by, int bx, int tx, int ty, int tid) {
    constexpr int DOUT = DIN - 2;
    constexpr int RPT = (DOUT + 7) / 8;
    const int j = 2 * tx;
    const int r0 = ty * RPT;
    int r1 = r0 + RPT; if (r1 > DOUT) r1 = DOUT;
    const float* pin = in + r0 * DIN + j;
    float2 a0 = *(const float2*)(pin),       a1 = *(const float2*)(pin + 2);
    float2 b0 = *(const float2*)(pin + DIN), b1 = *(const float2*)(pin + DIN + 2);
    const float* nrow = pin + 2 * DIN;
    float* orow = out + r0 * DOUT + j;
    bool c0ok = true, c1ok = true;
    if (BORDER) {
        c0ok = (unsigned)(bx + j - HOUT) < 512u;
        c1ok = (unsigned)(bx + j + 1 - HOUT) < 512u;
    }
    for (int i = r0; i < r1; ++i) {
        const float2 c0 = *(const float2*)(nrow), c1 = *(const float2*)(nrow + 2);
        const float v1 = fminf(fminf(a0.y, b0.y), c0.y);   // vert min col j+1
        const float v2 = fminf(fminf(a1.x, b1.x), c1.x);   // vert min col j+2
        float o0 = fminf(v1, fminf(b0.x, b1.x));
        float o1 = fminf(v2, fminf(b0.y, b1.y));
        if (BORDER) {
            const bool rok = (unsigned)(by + i - HOUT) < 512u;
            if (!rok | !c0ok) o0 = BIGF;
            if (!rok | !c1ok) o1 = BIGF;
        }
        *(float2*)orow = make_float2(o0, o1);
        a0 = b0; a1 = b1; b0 = c0; b1 = c1;
        nrow += DIN; orow += DOUT;
    }
    // extra columns 64..DOUT-1 (scalar, scattered)
    constexpr int EX = (DOUT - 64) * DOUT;
    for (int e = tid; e < EX; e += NT) {
        const int q = e / DOUT, jj = 64 + q, i = e - q * DOUT;
        float v = fminf(fminf(in[i * DIN + jj + 1], in[(i + 1) * DIN + jj + 1]),
                        in[(i + 2) * DIN + jj + 1]);
        v = fminf(v, fminf(in[(i + 1) * DIN + jj], in[(i + 1) * DIN + jj + 2]));
        if (BORDER) {
            const int gr = by + i - HOUT, gc = bx + jj - HOUT;
            if ((unsigned)gr >= 512u || (unsigned)gc >= 512u) v = BIGF;
        }
        out[i * DOUT + jj] = v;
    }
}

// update: delta = gelu(Ek - dilate(Ek1)); sk += gelu(delta - sk*delta)
// Ek: DK x DK halo HK; Ek1: (DK-2)^2 halo HK-1. Pair columns, rolling row-maxes.
template<int DK, int HK, bool BORDER>
__device__ __forceinline__ void upd_pair(const float* __restrict__ ek,
                                         const float* __restrict__ ek1,
                                         float2* sk, int by, int bx, int tx, int ty) {
    constexpr int DK1 = DK - 2, H1 = HK - 1;
    const int j = 2 * tx, r0 = ty * 8;
    bool okL = true, okR = true;
    if (BORDER) {
        okL = (unsigned)(bx + j - 1) < 512u;
        okR = (unsigned)(bx + j + 2) < 512u;
    }
    auto rowpair = [&](int ri, bool rok) -> float2 {
        const float* p = ek1 + ri * DK1 + (j + H1 - 1);
        float v0, v1, v2, v3;
        if constexpr ((H1 & 1) == 1) {
            const float2 u = *(const float2*)(p);
            const float2 w = *(const float2*)(p + 2);
            v0 = u.x; v1 = u.y; v2 = w.x; v3 = w.y;
        } else {
            const float2 u = *(const float2*)(p + 1);
            v0 = p[0]; v1 = u.x; v2 = u.y; v3 = p[3];
        }
        if (BORDER) { if (!okL) v0 = -BIGF; if (!okR) v3 = -BIGF; }
        const float m = fmaxf(v1, v2);
        float2 rm = make_float2(fmaxf(m, v0), fmaxf(m, v3));
        if (BORDER && !rok) { rm.x = -BIGF; rm.y = -BIGF; }
        return rm;
    };
    float2 rma = rowpair(r0 + H1 - 1, !BORDER || ((unsigned)(by + r0 - 1) < 512u));
    float2 rmb = rowpair(r0 + H1, true);
    #pragma unroll
    for (int q = 0; q < 8; ++q) {
        const int r = r0 + q;
        const float2 rmc = rowpair(r + H1 + 1, !BORDER || ((unsigned)(by + r + 1) < 512u));
        const float o0 = fmaxf(fmaxf(rma.x, rmb.x), rmc.x);
        const float o1 = fmaxf(fmaxf(rma.y, rmb.y), rmc.y);
        const float* pc = ek + (r + HK) * DK + (j + HK);
        float e0, e1;
        if constexpr ((HK & 1) == 0) { const float2 u = *(const float2*)pc; e0 = u.x; e1 = u.y; }
        else { e0 = pc[0]; e1 = pc[1]; }
        const float d0 = gelu_exact(e0 - o0);
        const float d1 = gelu_exact(e1 - o1);
        float s0 = sk[q].x, s1 = sk[q].y;
        s0 += gelu_exact(d0 - s0 * d0);
        s1 += gelu_exact(d1 - s1 * d1);
        sk[q] = make_float2(s0, s1);
        rma = rmb; rmb = rmc;
    }
}

__device__ __forceinline__ float warpSum(float v) {
    #pragma unroll
    for (int o = 16; o; o >>= 1) v += __shfl_down_sync(0xffffffffu, v, o);
    return v;
}

// 4 fused soft-skel iterations. x (halo 6) -> E1..E5; skel in 8 float2 regs.
template<bool BORDER, bool RED>
__device__ __forceinline__ void fused_body(const float* __restrict__ sp,
                                           float* __restrict__ dp,
                                           const float* __restrict__ yt,
                                           const float* __restrict__ yp,
                                           float* sX, float* sY, float* s_red,
                                           int plane, int by, int bx,
                                           int tx, int ty) {
    const int tid = ty * 32 + tx;

    // Load x with halo 6 from padded global — zero predicates, float2.
    {
        const float* g0 = sp + (by - 6) * GP + (bx - 6);
        for (int r = ty; r < 76; r += 8) {
            const float2* grp = (const float2*)(g0 + r * GP);
            float2* srow = (float2*)(sX + r * 76);
            srow[tx] = grp[tx];
            if (tx < 6) srow[tx + 32] = grp[tx + 32];
        }
    }
    __syncthreads();

    erode_pair<76, 5, BORDER>(sX, sY, by, bx, tx, ty, tid);   // E1 (74, h5)
    __syncthreads();
    erode_pair<74, 4, BORDER>(sY, sX, by, bx, tx, ty, tid);   // E2 (72, h4)
    __syncthreads();

    float2 sk[8];
    const int r0 = ty * 8, j = 2 * tx;
    {
        const float* gs = &g_skel[plane * PLANE + (by + r0) * W + bx + j];
        #pragma unroll
        for (int q = 0; q < 8; ++q) sk[q] = *(const float2*)(gs + q * W);
    }
    upd_pair<74, 5, BORDER>(sY, sX, sk, by, bx, tx, ty);      // step 1
    __syncthreads();
    erode_pair<72, 3, BORDER>(sX, sY, by, bx, tx, ty, tid);   // E3 (70, h3)
    __syncthreads();
    upd_pair<72, 4, BORDER>(sX, sY, sk, by, bx, tx, ty);      // step 2
    __syncthreads();
    erode_pair<70, 2, BORDER>(sY, sX, by, bx, tx, ty, tid);   // E4 (68, h2)
    __syncthreads();
    upd_pair<70, 3, BORDER>(sY, sX, sk, by, bx, tx, ty);      // step 3
    __syncthreads();
    erode_pair<68, 1, BORDER>(sX, sY, by, bx, tx, ty, tid);   // E5 (66, h1)
    __syncthreads();
    upd_pair<68, 2, BORDER>(sX, sY, sk, by, bx, tx, ty);      // step 4

    if (!RED) {
        float* gs = &g_skel[plane * PLANE + (by + r0) * W + bx + j];
        float* gd = dp + (by + r0) * GP + bx + j;
        #pragma unroll
        for (int q = 0; q < 8; ++q) {
            *(float2*)(gs + q * W) = sk[q];
            *(float2*)(gd + q * GP) = *(const float2*)(sX + (r0 + q + 2) * 68 + j + 2);
        }
    } else {
        float a0 = 0.f, a1 = 0.f, a2 = 0.f, a3 = 0.f, a4 = 0.f, a5 = 0.f, a6 = 0.f;
        const int gi0 = (plane & 15) * PLANE + (by + r0) * W + bx + j;
        if (plane < HALF) {
            #pragma unroll
            for (int q = 0; q < 8; ++q) {
                const float2 t = *(const float2*)(yt + gi0 + q * W);
                const float2 p = *(const float2*)(yp + gi0 + q * W);
                const float2 s = sk[q];
                a0 += t.x + t.y;
                a1 += p.x + p.y;
                a2 += t.x * p.x + t.y * p.y;
                a3 += s.x + s.y;
                a4 += s.x * t.x + s.y * t.y;
            }
        } else {
            #pragma unroll
            for (int q = 0; q < 8; ++q) {
                const float2 p = *(const float2*)(yp + gi0 + q * W);
                const float2 s = sk[q];
                a5 += s.x + s.y;
                a6 += s.x * p.x + s.y * p.y;
            }
        }
        float v[7] = {a0, a1, a2, a3, a4, a5, a6};
        const int lane = tid & 31, wrp = tid >> 5;
        #pragma unroll
        for (int k = 0; k < 7; k++) {
            const float s = warpSum(v[k]);
            if (lane == 0) s_red[wrp * 8 + k] = s;
        }
        __syncthreads();
        if (wrp == 0) {
            const int bid = plane * 64 + (by >> 6) * 8 + (bx >> 6);
            #pragma unroll
            for (int k = 0; k < 7; k++) {
                float s = (lane < 8) ? s_red[lane * 8 + k] : 0.f;
                s = warpSum(s);
                if (lane == 0) g_part[bid * 8 + k] = s;
            }
        }
    }
}

__global__ __launch_bounds__(NT) void fused_kernel(int readA) {
    __shared__ __align__(16) float sX[76 * 76];
    __shared__ __align__(16) float sY[74 * 74];
    const float* src = readA ? g_bufA : g_bufB;
    float* dst = readA ? g_bufB : g_bufA;
    const int plane = blockIdx.z;
    const int by = blockIdx.y * 64, bx = blockIdx.x * 64;
    const float* sp = src + plane * PSZ + BOFF;
    float* dp = dst + plane * PSZ + BOFF;
    const bool border = (blockIdx.x == 0) | (blockIdx.x == 7) | (blockIdx.y == 0) | (blockIdx.y == 7);
    if (border) fused_body<true , false>(sp, dp, nullptr, nullptr, sX, sY, nullptr,
                                         plane, by, bx, threadIdx.x, threadIdx.y);
    else        fused_body<false, false>(sp, dp, nullptr, nullptr, sX, sY, nullptr,
                                         plane, by, bx, threadIdx.x, threadIdx.y);
}

__global__ __launch_bounds__(NT) void fused_red_kernel(const float* __restrict__ yt,
                                                       const float* __restrict__ yp,
                                                       int readA) {
    __shared__ __align__(16) float sX[76 * 76];
    __shared__ __align__(16) float sY[74 * 74];
    __shared__ float s_red[64];
    const float* src = readA ? g_bufA : g_bufB;
    float* dst = readA ? g_bufB : g_bufA;
    const int plane = blockIdx.z;
    const int by = blockIdx.y * 64, bx = blockIdx.x * 64;
    const float* sp = src + plane * PSZ + BOFF;
    float* dp = dst + plane * PSZ + BOFF;
    const bool border = (blockIdx.x == 0) | (blockIdx.x == 7) | (blockIdx.y == 0) | (blockIdx.y == 7);
    if (border) fused_body<true , true>(sp, dp, yt, yp, sX, sY, s_red,
                                        plane, by, bx, threadIdx.x, threadIdx.y);
    else        fused_body<false, true>(sp, dp, yt, yp, sX, sY, s_red,
                                        plane, by, bx, threadIdx.x, threadIdx.y);
}

// ---------------------------------------------------------------------------
// Final: sum 2048 partials, compute loss scalar
// ---------------------------------------------------------------------------
__global__ __launch_bounds__(256) void final_kernel(float* __restrict__ out) {
    float a[7] = {0.f, 0.f, 0.f, 0.f, 0.f, 0.f, 0.f};
    for (int b = threadIdx.x; b < NBLOCKS; b += 256) {
        #pragma unroll
        for (int j = 0; j < 7; j++) a[j] += g_part[b * 8 + j];
    }
    __shared__ float shm[8][8];
    const int lane = threadIdx.x & 31, wrp = threadIdx.x >> 5;
    #pragma unroll
    for (int j = 0; j < 7; j++) {
        const float v = warpSum(a[j]);
        if (lane == 0) shm[wrp][j] = v;
    }
    __syncthreads();
    if (wrp == 0) {
        float res[7];
        #pragma unroll
        for (int j = 0; j < 7; j++) {
            float v = (lane < 8) ? shm[lane][j] : 0.f;
            res[j] = warpSum(v);
        }
        if (lane == 0) {
            const float S_t = res[0], S_p = res[1], S_tp = res[2];
            const float S_sp = res[3], S_spt = res[4];
            const float S_st = res[5], S_stp = res[6];
            const float dice  = 1.0f - (2.0f * S_tp + 1.0f) / (S_t + S_p + 1.0f);
            const float tprec = (S_spt + 1.0f) / (S_sp + 1.0f);
            const float tsens = (S_stp + 1.0f) / (S_st + 1.0f);
            const float cl    = 1.0f - 2.0f * (tprec * tsens) / (tprec + tsens);
            out[0] = 0.7f * dice + 0.3f * cl;
        }
    }
}

// ---------------------------------------------------------------------------
extern "C" void kernel_launch(void* const* d_in, const int* in_sizes, int n_in,
                              void* d_out, int out_size) {
    const float* y_true = (const float*)d_in[0];
    const float* y_pred = (const float*)d_in[1];

    dim3 grid(8, 8, NPLANES);
    dim3 blk_init(64, 4);
    dim3 blk(32, 8);

    fill_kernel<<<1024, 256>>>();
    init_kernel<<<grid, blk_init>>>(y_true, y_pred);
    fused_kernel<<<grid, blk>>>(1);      // steps 1-4   A -> B
    fused_kernel<<<grid, blk>>>(0);      // steps 5-8   B -> A
    fused_kernel<<<grid, blk>>>(1);      // steps 9-12  A -> B
    fused_kernel<<<grid, blk>>>(0);      // steps 13-16 B -> A
    fused_red_kernel<<<grid, blk>>>(y_true, y_pred, 1);  // steps 17-20 + sums
    final_kernel<<<1, 256>>>((float*)d_out);
}

// round 10
// speedup vs baseline: 2.3787x; 1.1384x over previous
#include <cuda_runtime.h>

#define W 512
#define PLANE (512*512)
#define NPLANES 32
#define HALF 16
#define TOTAL (NPLANES*PLANE)
#define GP 524                  // padded pitch (6 + 512 + 6)
#define GR 524
#define PSZ (GP*GR)
#define BOFF (6*GP + 6)         // offset of pixel (0,0) in a padded plane
#define NT 256
#define NBLOCKS 2048
#define BIGF 1e30f

// Scratch (device globals; no allocation allowed)
__device__ __align__(16) float g_bufA[NPLANES * PSZ];
__device__ __align__(16) float g_bufB[NPLANES * PSZ];
__device__ __align__(16) float g_skel[TOTAL];
__device__ float g_part[NBLOCKS * 8];

// gelu via Abramowitz-Stegun 7.1.26 erf (abs err <= 1.5e-7):
// erf(t) = 1 - (a1 k + ... + a5 k^5) exp(-t^2), k = 1/(1 + p t), t >= 0
__device__ __forceinline__ float gelu_exact(float x) {
    const float t = fabsf(x) * 0.70710678118654752f;
    const float k = __fdividef(1.0f, fmaf(0.3275911f, t, 1.0f));
    float p = fmaf(1.061405429f, k, -1.453152027f);
    p = fmaf(p, k, 1.421413741f);
    p = fmaf(p, k, -0.284496736f);
    p = fmaf(p, k, 0.254829592f);
    p = p * k;
    const float e = __expf(-t * t);
    const float erf_abs = fmaf(-p, e, 1.0f);
    const float er = copysignf(erf_abs, x);
    return 0.5f * x * (1.0f + er);
}

// ---------------------------------------------------------------------------
// Fill both padded buffers with +BIG (erode-friendly pad ring, written once).
// ---------------------------------------------------------------------------
__global__ __launch_bounds__(256) void fill_kernel() {
    const int n4 = (NPLANES * PSZ) / 4;
    const float4 v = make_float4(BIGF, BIGF, BIGF, BIGF);
    for (int i = blockIdx.x * blockDim.x + threadIdx.x; i < n4;
         i += gridDim.x * blockDim.x) {
        reinterpret_cast<float4*>(g_bufA)[i] = v;
        reinterpret_cast<float4*>(g_bufB)[i] = v;
    }
}

// ---------------------------------------------------------------------------
// INIT: skel = gelu(img - dilate(erode(img))); padded bufA = img
// ---------------------------------------------------------------------------
template<bool BORDER>
__device__ __forceinline__ void init_body(const float* __restrict__ src,
                                          float* s_img, float* s_e1,
                                          int plane, int by, int bx,
                                          int tx, int ty) {
    const int tid = ty * 64 + tx;

    for (int r = ty; r < 68; r += 4) {
        float* srow = s_img + r * 70;
        const int gr = by + r - 2;
        {
            const int gc = bx + tx - 2;
            float v;
            if (!BORDER) v = src[gr * W + gc];
            else v = ((unsigned)gr < 512u && (unsigned)gc < 512u) ? src[gr * W + gc] : BIGF;
            srow[tx] = v;
        }
        if (tx < 4) {
            const int gc = bx + tx + 62;
            float v;
            if (!BORDER) v = src[gr * W + gc];
            else v = ((unsigned)gr < 512u && (unsigned)gc < 512u) ? src[gr * W + gc] : BIGF;
            srow[tx + 64] = v;
        }
    }
    __syncthreads();

    // E1 = erode(img) on 66x66 (halo 1); out-of-image -> -BIG (feeds dilate only)
    {
        const int r0 = ty * 17;
        int r1 = r0 + 17; if (r1 > 66) r1 = 66;
        const int j = tx;
        float a = s_img[r0 * 70 + j + 1];
        float b = s_img[(r0 + 1) * 70 + j + 1];
        for (int i = r0; i < r1; ++i) {
            const float cn = s_img[(i + 2) * 70 + j + 1];
            float v = fminf(fminf(a, b), cn);
            v = fminf(v, fminf(s_img[(i + 1) * 70 + j], s_img[(i + 1) * 70 + j + 2]));
            if (BORDER) {
                const int gr = by + i - 1, gc = bx + j - 1;
                if ((unsigned)gr >= 512u || (unsigned)gc >= 512u) v = -BIGF;
            }
            s_e1[i * 68 + j] = v;
            a = b; b = cn;
        }
        for (int e = tid; e < 132; e += NT) {
            const int q = e / 66, jj = 64 + q, i = e - q * 66;
            float v = fminf(fminf(s_img[i * 70 + jj + 1], s_img[(i + 1) * 70 + jj + 1]),
                            s_img[(i + 2) * 70 + jj + 1]);
            v = fminf(v, fminf(s_img[(i + 1) * 70 + jj], s_img[(i + 1) * 70 + jj + 2]));
            if (BORDER) {
                const int gr = by + i - 1, gc = bx + jj - 1;
                if ((unsigned)gr >= 512u || (unsigned)gc >= 512u) v = -BIGF;
            }
            s_e1[i * 68 + jj] = v;
        }
    }
    __syncthreads();

    // open = dilate(E1); skel = gelu(img - open); store img to padded bufA
    {
        const int r0 = ty * 16;
        const int c = tx;
        float x0 = s_e1[r0 * 68 + c], x1 = s_e1[r0 * 68 + c + 1], x2 = s_e1[r0 * 68 + c + 2];
        float rma = fmaxf(fmaxf(x0, x1), x2);
        x0 = s_e1[(r0 + 1) * 68 + c]; x1 = s_e1[(r0 + 1) * 68 + c + 1]; x2 = s_e1[(r0 + 1) * 68 + c + 2];
        float rmb = fmaxf(fmaxf(x0, x1), x2);
        float* dA = g_bufA + plane * PSZ + BOFF;
        for (int r = r0; r < r0 + 16; ++r) {
            x0 = s_e1[(r + 2) * 68 + c]; x1 = s_e1[(r + 2) * 68 + c + 1]; x2 = s_e1[(r + 2) * 68 + c + 2];
            const float rmc = fmaxf(fmaxf(x0, x1), x2);
            const float open_ = fmaxf(fmaxf(rma, rmb), rmc);
            const float img = s_img[(r + 2) * 70 + c + 2];
            g_skel[plane * PLANE + (by + r) * W + (bx + c)] = gelu_exact(img - open_);
            dA[(by + r) * GP + (bx + c)] = img;
            rma = rmb; rmb = rmc;
        }
    }
}

__global__ __launch_bounds__(NT) void init_kernel(const float* __restrict__ yt,
                                                  const float* __restrict__ yp) {
    __shared__ __align__(16) float s_img[70 * 70];
    __shared__ __align__(16) float s_e1[68 * 68];
    const int plane = blockIdx.z;
    const float* src = ((plane < HALF) ? yp : yt) + (plane & 15) * PLANE;
    const int by = blockIdx.y * 64, bx = blockIdx.x * 64;
    const bool border = (blockIdx.x == 0) | (blockIdx.x == 7) | (blockIdx.y == 0) | (blockIdx.y == 7);
    if (border) init_body<true >(src, s_img, s_e1, plane, by, bx, threadIdx.x, threadIdx.y);
    else        init_body<false>(src, s_img, s_e1, plane, by, bx, threadIdx.x, threadIdx.y);
}

// ---------------------------------------------------------------------------
// Fused 4-step kernel building blocks — pairwise (float2), block (32,8).
// ---------------------------------------------------------------------------
template<int DIN, int HOUT, bool BORDER>
__device__ __forceinline__ void erode_pair(const float* __restrict__ in,
                                           float* __restrict__ out,
                                           int by, int bx, int tx, int ty, int tid) {
    constexpr int DOUT = DIN - 2;
    constexpr int RPT = (DOUT + 7) / 8;
    const int j = 2 * tx;
    const int r0 = ty * RPT;
    int r1 = r0 + RPT; if (r1 > DOUT) r1 = DOUT;
    const float* pin = in + r0 * DIN + j;
    float2 a0 = *(const float2*)(pin),       a1 = *(const float2*)(pin + 2);
    float2 b0 = *(const float2*)(pin + DIN), b1 = *(const float2*)(pin + DIN + 2);
    const float* nrow = pin + 2 * DIN;
    float* orow = out + r0 * DOUT + j;
    bool c0ok = true, c1ok = true;
    if (BORDER) {
        c0ok = (unsigned)(bx + j - HOUT) < 512u;
        c1ok = (unsigned)(bx + j + 1 - HOUT) < 512u;
    }
    for (int i = r0; i < r1; ++i) {
        const float2 c0 = *(const float2*)(nrow), c1 = *(const float2*)(nrow + 2);
        const float v1 = fminf(fminf(a0.y, b0.y), c0.y);   // vert min col j+1
        const float v2 = fminf(fminf(a1.x, b1.x), c1.x);   // vert min col j+2
        float o0 = fminf(v1, fminf(b0.x, b1.x));
        float o1 = fminf(v2, fminf(b0.y, b1.y));
        if (BORDER) {
            const bool rok = (unsigned)(by + i - HOUT) < 512u;
            if (!rok | !c0ok) o0 = BIGF;
            if (!rok | !c1ok) o1 = BIGF;
        }
        *(float2*)orow = make_float2(o0, o1);
        a0 = b0; a1 = b1; b0 = c0; b1 = c1;
        nrow += DIN; orow += DOUT;
    }
    constexpr int EX = (DOUT - 64) * DOUT;
    for (int e = tid; e < EX; e += NT) {
        const int q = e / DOUT, jj = 64 + q, i = e - q * DOUT;
        float v = fminf(fminf(in[i * DIN + jj + 1], in[(i + 1) * DIN + jj + 1]),
                        in[(i + 2) * DIN + jj + 1]);
        v = fminf(v, fminf(in[(i + 1) * DIN + jj], in[(i + 1) * DIN + jj + 2]));
        if (BORDER) {
            const int gr = by + i - HOUT, gc = bx + jj - HOUT;
            if ((unsigned)gr >= 512u || (unsigned)gc >= 512u) v = BIGF;
        }
        out[i * DOUT + jj] = v;
    }
}

template<int DK, int HK, bool BORDER>
__device__ __forceinline__ void upd_pair(const float* __restrict__ ek,
                                         const float* __restrict__ ek1,
                                         float2* sk, int by, int bx, int tx, int ty) {
    constexpr int DK1 = DK - 2, H1 = HK - 1;
    const int j = 2 * tx, r0 = ty * 8;
    bool okL = true, okR = true;
    if (BORDER) {
        okL = (unsigned)(bx + j - 1) < 512u;
        okR = (unsigned)(bx + j + 2) < 512u;
    }
    auto rowpair = [&](int ri, bool rok) -> float2 {
        const float* p = ek1 + ri * DK1 + (j + H1 - 1);
        float v0, v1, v2, v3;
        if constexpr ((H1 & 1) == 1) {
            const float2 u = *(const float2*)(p);
            const float2 w = *(const float2*)(p + 2);
            v0 = u.x; v1 = u.y; v2 = w.x; v3 = w.y;
        } else {
            const float2 u = *(const float2*)(p + 1);
            v0 = p[0]; v1 = u.x; v2 = u.y; v3 = p[3];
        }
        if (BORDER) { if (!okL) v0 = -BIGF; if (!okR) v3 = -BIGF; }
        const float m = fmaxf(v1, v2);
        float2 rm = make_float2(fmaxf(m, v0), fmaxf(m, v3));
        if (BORDER && !rok) { rm.x = -BIGF; rm.y = -BIGF; }
        return rm;
    };
    float2 rma = rowpair(r0 + H1 - 1, !BORDER || ((unsigned)(by + r0 - 1) < 512u));
    float2 rmb = rowpair(r0 + H1, true);
    #pragma unroll
    for (int q = 0; q < 8; ++q) {
        const int r = r0 + q;
        const float2 rmc = rowpair(r + H1 + 1, !BORDER || ((unsigned)(by + r + 1) < 512u));
        const float o0 = fmaxf(fmaxf(rma.x, rmb.x), rmc.x);
        const float o1 = fmaxf(fmaxf(rma.y, rmb.y), rmc.y);
        const float* pc = ek + (r + HK) * DK + (j + HK);
        float e0, e1;
        if constexpr ((HK & 1) == 0) { const float2 u = *(const float2*)pc; e0 = u.x; e1 = u.y; }
        else { e0 = pc[0]; e1 = pc[1]; }
        const float d0 = gelu_exact(e0 - o0);
        const float d1 = gelu_exact(e1 - o1);
        float s0 = sk[q].x, s1 = sk[q].y;
        s0 += gelu_exact(d0 - s0 * d0);
        s1 += gelu_exact(d1 - s1 * d1);
        sk[q] = make_float2(s0, s1);
        rma = rmb; rmb = rmc;
    }
}

__device__ __forceinline__ float warpSum(float v) {
    #pragma unroll
    for (int o = 16; o; o >>= 1) v += __shfl_down_sync(0xffffffffu, v, o);
    return v;
}

// 4 fused soft-skel iterations. x (halo 6) -> E1..E5; skel in 8 float2 regs.
template<bool BORDER, bool RED>
__device__ __forceinline__ void fused_body(const float* __restrict__ sp,
                                           float* __restrict__ dp,
                                           const float* __restrict__ yt,
                                           const float* __restrict__ yp,
                                           float* sX, float* sY, float* s_red,
                                           int plane, int by, int bx,
                                           int tx, int ty) {
    const int tid = ty * 32 + tx;

    // Load x with halo 6 from padded global — zero predicates, float2.
    {
        const float* g0 = sp + (by - 6) * GP + (bx - 6);
        for (int r = ty; r < 76; r += 8) {
            const float2* grp = (const float2*)(g0 + r * GP);
            float2* srow = (float2*)(sX + r * 76);
            srow[tx] = grp[tx];
            if (tx < 6) srow[tx + 32] = grp[tx + 32];
        }
    }
    __syncthreads();

    erode_pair<76, 5, BORDER>(sX, sY, by, bx, tx, ty, tid);   // E1 (74, h5)
    __syncthreads();
    erode_pair<74, 4, BORDER>(sY, sX, by, bx, tx, ty, tid);   // E2 (72, h4)
    __syncthreads();

    float2 sk[8];
    const int r0 = ty * 8, j = 2 * tx;
    {
        const float* gs = &g_skel[plane * PLANE + (by + r0) * W + bx + j];
        #pragma unroll
        for (int q = 0; q < 8; ++q) sk[q] = *(const float2*)(gs + q * W);
    }
    upd_pair<74, 5, BORDER>(sY, sX, sk, by, bx, tx, ty);      // step 1
    __syncthreads();
    erode_pair<72, 3, BORDER>(sX, sY, by, bx, tx, ty, tid);   // E3 (70, h3)
    __syncthreads();
    upd_pair<72, 4, BORDER>(sX, sY, sk, by, bx, tx, ty);      // step 2
    __syncthreads();
    erode_pair<70, 2, BORDER>(sY, sX, by, bx, tx, ty, tid);   // E4 (68, h2)
    __syncthreads();
    upd_pair<70, 3, BORDER>(sY, sX, sk, by, bx, tx, ty);      // step 3
    __syncthreads();
    erode_pair<68, 1, BORDER>(sX, sY, by, bx, tx, ty, tid);   // E5 (66, h1)
    __syncthreads();
    upd_pair<68, 2, BORDER>(sX, sY, sk, by, bx, tx, ty);      // step 4

    if (!RED) {
        float* gs = &g_skel[plane * PLANE + (by + r0) * W + bx + j];
        float* gd = dp + (by + r0) * GP + bx + j;
        #pragma unroll
        for (int q = 0; q < 8; ++q) {
            *(float2*)(gs + q * W) = sk[q];
            *(float2*)(gd + q * GP) = *(const float2*)(sX + (r0 + q + 2) * 68 + j + 2);
        }
    } else {
        float a0 = 0.f, a1 = 0.f, a2 = 0.f, a3 = 0.f, a4 = 0.f, a5 = 0.f, a6 = 0.f;
        const int gi0 = (plane & 15) * PLANE + (by + r0) * W + bx + j;
        if (plane < HALF) {
            #pragma unroll
            for (int q = 0; q < 8; ++q) {
                const float2 t = *(const float2*)(yt + gi0 + q * W);
                const float2 p = *(const float2*)(yp + gi0 + q * W);
                const float2 s = sk[q];
                a0 += t.x + t.y;
                a1 += p.x + p.y;
                a2 += t.x * p.x + t.y * p.y;
                a3 += s.x + s.y;
                a4 += s.x * t.x + s.y * t.y;
            }
        } else {
            #pragma unroll
            for (int q = 0; q < 8; ++q) {
                const float2 p = *(const float2*)(yp + gi0 + q * W);
                const float2 s = sk[q];
                a5 += s.x + s.y;
                a6 += s.x * p.x + s.y * p.y;
            }
        }
        float v[7] = {a0, a1, a2, a3, a4, a5, a6};
        const int lane = tid & 31, wrp = tid >> 5;
        #pragma unroll
        for (int k = 0; k < 7; k++) {
            const float s = warpSum(v[k]);
            if (lane == 0) s_red[wrp * 8 + k] = s;
        }
        __syncthreads();
        if (wrp == 0) {
            const int bid = plane * 64 + (by >> 6) * 8 + (bx >> 6);
            #pragma unroll
            for (int k = 0; k < 7; k++) {
                float s = (lane < 8) ? s_red[lane * 8 + k] : 0.f;
                s = warpSum(s);
                if (lane == 0) g_part[bid * 8 + k] = s;
            }
        }
    }
}

__global__ __launch_bounds__(NT, 5) void fused_kernel(int readA) {
    __shared__ __align__(16) float sX[76 * 76];
    __shared__ __align__(16) float sY[74 * 74];
    const float* src = readA ? g_bufA : g_bufB;
    float* dst = readA ? g_bufB : g_bufA;
    const int plane = blockIdx.z;
    const int by = blockIdx.y * 64, bx = blockIdx.x * 64;
    const float* sp = src + plane * PSZ + BOFF;
    float* dp = dst + plane * PSZ + BOFF;
    const bool border = (blockIdx.x == 0) | (blockIdx.x == 7) | (blockIdx.y == 0) | (blockIdx.y == 7);
    if (border) fused_body<true , false>(sp, dp, nullptr, nullptr, sX, sY, nullptr,
                                         plane, by, bx, threadIdx.x, threadIdx.y);
    else        fused_body<false, false>(sp, dp, nullptr, nullptr, sX, sY, nullptr,
                                         plane, by, bx, threadIdx.x, threadIdx.y);
}

__global__ __launch_bounds__(NT, 5) void fused_red_kernel(const float* __restrict__ yt,
                                                          const float* __restrict__ yp,
                                                          int readA) {
    __shared__ __align__(16) float sX[76 * 76];
    __shared__ __align__(16) float sY[74 * 74];
    __shared__ float s_red[64];
    const float* src = readA ? g_bufA : g_bufB;
    float* dst = readA ? g_bufB : g_bufA;
    const int plane = blockIdx.z;
    const int by = blockIdx.y * 64, bx = blockIdx.x * 64;
    const float* sp = src + plane * PSZ + BOFF;
    float* dp = dst + plane * PSZ + BOFF;
    const bool border = (blockIdx.x == 0) | (blockIdx.x == 7) | (blockIdx.y == 0) | (blockIdx.y == 7);
    if (border) fused_body<true , true>(sp, dp, yt, yp, sX, sY, s_red,
                                        plane, by, bx, threadIdx.x, threadIdx.y);
    else        fused_body<false, true>(sp, dp, yt, yp, sX, sY, s_red,
                                        plane, by, bx, threadIdx.x, threadIdx.y);
}

// ---------------------------------------------------------------------------
// Final: sum 2048 partials, compute loss scalar
// ---------------------------------------------------------------------------
__global__ __launch_bounds__(256) void final_kernel(float* __restrict__ out) {
    float a[7] = {0.f, 0.f, 0.f, 0.f, 0.f, 0.f, 0.f};
    for (int b = threadIdx.x; b < NBLOCKS; b += 256) {
        #pragma unroll
        for (int j = 0; j < 7; j++) a[j] += g_part[b * 8 + j];
    }
    __shared__ float shm[8][8];
    const int lane = threadIdx.x & 31, wrp = threadIdx.x >> 5;
    #pragma unroll
    for (int j = 0; j < 7; j++) {
        const float v = warpSum(a[j]);
        if (lane == 0) shm[wrp][j] = v;
    }
    __syncthreads();
    if (wrp == 0) {
        float res[7];
        #pragma unroll
        for (int j = 0; j < 7; j++) {
            float v = (lane < 8) ? shm[lane][j] : 0.f;
            res[j] = warpSum(v);
        }
        if (lane == 0) {
            const float S_t = res[0], S_p = res[1], S_tp = res[2];
            const float S_sp = res[3], S_spt = res[4];
            const float S_st = res[5], S_stp = res[6];
            const float dice  = 1.0f - (2.0f * S_tp + 1.0f) / (S_t + S_p + 1.0f);
            const float tprec = (S_spt + 1.0f) / (S_sp + 1.0f);
            const float tsens = (S_stp + 1.0f) / (S_st + 1.0f);
            const float cl    = 1.0f - 2.0f * (tprec * tsens) / (tprec + tsens);
            out[0] = 0.7f * dice + 0.3f * cl;
        }
    }
}

// ---------------------------------------------------------------------------
extern "C" void kernel_launch(void* const* d_in, const int* in_sizes, int n_in,
                              void* d_out, int out_size) {
    const float* y_true = (const float*)d_in[0];
    const float* y_pred = (const float*)d_in[1];

    dim3 grid(8, 8, NPLANES);
    dim3 blk_init(64, 4);
    dim3 blk(32, 8);

    fill_kernel<<<1024, 256>>>();
    init_kernel<<<grid, blk_init>>>(y_true, y_pred);
    fused_kernel<<<grid, blk>>>(1);      // steps 1-4   A -> B
    fused_kernel<<<grid, blk>>>(0);      // steps 5-8   B -> A
    fused_kernel<<<grid, blk>>>(1);      // steps 9-12  A -> B
    fused_kernel<<<grid, blk>>>(0);      // steps 13-16 B -> A
    fused_red_kernel<<<grid, blk>>>(y_true, y_pred, 1);  // steps 17-20 + sums
    final_kernel<<<1, 256>>>((float*)d_out);
}

// round 11
// speedup vs baseline: 3.1299x; 1.3158x over previous
#include <cuda_runtime.h>

#define W 512
#define PLANE (512*512)
#define NPLANES 32
#define HALF 16
#define TOTAL (NPLANES*PLANE)
#define GP 524                  // padded pitch (6 + 512 + 6)
#define GR 524
#define PSZ (GP*GR)
#define BOFF (6*GP + 6)         // offset of pixel (0,0) in a padded plane
#define NT 256
#define NBLOCKS 2048
#define BIGF 1e30f

// Scratch (device globals; no allocation allowed)
__device__ __align__(16) float g_bufA[NPLANES * PSZ];
__device__ __align__(16) float g_bufB[NPLANES * PSZ];
__device__ __align__(16) float g_skel[TOTAL];
__device__ float g_part[NBLOCKS * 8];

// ---------------------------------------------------------------------------
// gelu via Abramowitz-Stegun 7.1.26 erf (abs err <= 1.5e-7).
// Scalar version (init kernel) + packed f32x2 pair version (fused kernels).
// ---------------------------------------------------------------------------
__device__ __forceinline__ float gelu_exact(float x) {
    const float t = fabsf(x) * 0.70710678118654752f;
    const float k = __fdividef(1.0f, fmaf(0.3275911f, t, 1.0f));
    float p = fmaf(1.061405429f, k, -1.453152027f);
    p = fmaf(p, k, 1.421413741f);
    p = fmaf(p, k, -0.284496736f);
    p = fmaf(p, k, 0.254829592f);
    p = p * k;
    const float e = __expf(-t * t);
    const float erf_abs = fmaf(-p, e, 1.0f);
    const float h = 0.5f * x;
    return fmaf(fabsf(h), erf_abs, h);   // = 0.5x(1 + sign(x) erf_abs)
}

// f32x2 helpers (PTX-only packed fp32; sm_100+)
__device__ __forceinline__ unsigned long long pk2(float a, float b) {
    unsigned long long r;
    asm("mov.b64 %0, {%1, %2};" : "=l"(r) : "f"(a), "f"(b));
    return r;
}
__device__ __forceinline__ float2 upk2(unsigned long long v) {
    float a, b;
    asm("mov.b64 {%0, %1}, %2;" : "=f"(a), "=f"(b) : "l"(v));
    return make_float2(a, b);
}
__device__ __forceinline__ unsigned long long fma2_(unsigned long long a,
                                                    unsigned long long b,
                                                    unsigned long long c) {
    unsigned long long d;
    asm("fma.rn.f32x2 %0, %1, %2, %3;" : "=l"(d) : "l"(a), "l"(b), "l"(c));
    return d;
}
__device__ __forceinline__ unsigned long long mul2_(unsigned long long a,
                                                    unsigned long long b) {
    unsigned long long d;
    asm("mul.rn.f32x2 %0, %1, %2;" : "=l"(d) : "l"(a), "l"(b));
    return d;
}
__device__ __forceinline__ float rcpa(float x) {
    float r; asm("rcp.approx.ftz.f32 %0, %1;" : "=f"(r) : "f"(x)); return r;
}
__device__ __forceinline__ float ex2a(float x) {
    float r; asm("ex2.approx.ftz.f32 %0, %1;" : "=f"(r) : "f"(x)); return r;
}

// Pairwise gelu: same A&S formula, polynomial/exp-scale packed as f32x2.
__device__ __forceinline__ float2 gelu2(float x0, float x1) {
    const float t0 = fabsf(x0) * 0.70710678118654752f;
    const float t1 = fabsf(x1) * 0.70710678118654752f;
    const float k0 = rcpa(fmaf(0.3275911f, t0, 1.0f));
    const float k1 = rcpa(fmaf(0.3275911f, t1, 1.0f));
    const unsigned long long kp = pk2(k0, k1);
    const unsigned long long tp = pk2(t0, t1);
    // negated poly so erf_abs = fma(p, e, 1)
    unsigned long long p = fma2_(pk2(-1.061405429f, -1.061405429f), kp,
                                 pk2(1.453152027f, 1.453152027f));
    p = fma2_(p, kp, pk2(-1.421413741f, -1.421413741f));
    p = fma2_(p, kp, pk2(0.284496736f, 0.284496736f));
    p = fma2_(p, kp, pk2(-0.254829592f, -0.254829592f));
    p = mul2_(p, kp);
    unsigned long long u = mul2_(tp, tp);
    u = mul2_(u, pk2(-1.4426950408889634f, -1.4426950408889634f)); // -t^2*log2(e)
    const float2 uf = upk2(u);
    const unsigned long long ep = pk2(ex2a(uf.x), ex2a(uf.y));
    const float2 ef = upk2(fma2_(p, ep, pk2(1.0f, 1.0f)));
    const float h0 = 0.5f * x0, h1 = 0.5f * x1;
    return make_float2(fmaf(fabsf(h0), ef.x, h0), fmaf(fabsf(h1), ef.y, h1));
}

// ---------------------------------------------------------------------------
// Fill ONLY the 6-wide halo rings of both padded buffers with +BIG.
// Interiors are always written before read (init -> bufA; fused -> dst).
// ---------------------------------------------------------------------------
__global__ __launch_bounds__(64) void fill_ring_kernel() {
    const int row = blockIdx.x;            // 0..GR-1
    const int plane = blockIdx.y;          // 0..31
    float* base = (blockIdx.z ? g_bufB : g_bufA) + plane * PSZ + row * GP;
    if (row < 6 || row >= 518) {
        for (int c = threadIdx.x; c < GP; c += 64) base[c] = BIGF;
    } else {
        const int tx = threadIdx.x;
        if (tx < 6) base[tx] = BIGF;            // cols 0..5
        else if (tx < 12) base[512 + tx] = BIGF; // cols 518..523
    }
}

// ---------------------------------------------------------------------------
// INIT: skel = gelu(img - dilate(erode(img))); padded bufA = img
// ---------------------------------------------------------------------------
template<bool BORDER>
__device__ __forceinline__ void init_body(const float* __restrict__ src,
                                          float* s_img, float* s_e1,
                                          int plane, int by, int bx,
                                          int tx, int ty) {
    const int tid = ty * 64 + tx;

    for (int r = ty; r < 68; r += 4) {
        float* srow = s_img + r * 70;
        const int gr = by + r - 2;
        {
            const int gc = bx + tx - 2;
            float v;
            if (!BORDER) v = src[gr * W + gc];
            else v = ((unsigned)gr < 512u && (unsigned)gc < 512u) ? src[gr * W + gc] : BIGF;
            srow[tx] = v;
        }
        if (tx < 4) {
            const int gc = bx + tx + 62;
            float v;
            if (!BORDER) v = src[gr * W + gc];
            else v = ((unsigned)gr < 512u && (unsigned)gc < 512u) ? src[gr * W + gc] : BIGF;
            srow[tx + 64] = v;
        }
    }
    __syncthreads();

    // E1 = erode(img) on 66x66 (halo 1); out-of-image -> -BIG (feeds dilate only)
    {
        const int r0 = ty * 17;
        int r1 = r0 + 17; if (r1 > 66) r1 = 66;
        const int j = tx;
        float a = s_img[r0 * 70 + j + 1];
        float b = s_img[(r0 + 1) * 70 + j + 1];
        for (int i = r0; i < r1; ++i) {
            const float cn = s_img[(i + 2) * 70 + j + 1];
            float v = fminf(fminf(a, b), cn);
            v = fminf(v, fminf(s_img[(i + 1) * 70 + j], s_img[(i + 1) * 70 + j + 2]));
            if (BORDER) {
                const int gr = by + i - 1, gc = bx + j - 1;
                if ((unsigned)gr >= 512u || (unsigned)gc >= 512u) v = -BIGF;
            }
            s_e1[i * 68 + j] = v;
            a = b; b = cn;
        }
        for (int e = tid; e < 132; e += NT) {
            const int q = e / 66, jj = 64 + q, i = e - q * 66;
            float v = fminf(fminf(s_img[i * 70 + jj + 1], s_img[(i + 1) * 70 + jj + 1]),
                            s_img[(i + 2) * 70 + jj + 1]);
            v = fminf(v, fminf(s_img[(i + 1) * 70 + jj], s_img[(i + 1) * 70 + jj + 2]));
            if (BORDER) {
                const int gr = by + i - 1, gc = bx + jj - 1;
                if ((unsigned)gr >= 512u || (unsigned)gc >= 512u) v = -BIGF;
            }
            s_e1[i * 68 + jj] = v;
        }
    }
    __syncthreads();

    // open = dilate(E1); skel = gelu(img - open); store img to padded bufA
    {
        const int r0 = ty * 16;
        const int c = tx;
        float x0 = s_e1[r0 * 68 + c], x1 = s_e1[r0 * 68 + c + 1], x2 = s_e1[r0 * 68 + c + 2];
        float rma = fmaxf(fmaxf(x0, x1), x2);
        x0 = s_e1[(r0 + 1) * 68 + c]; x1 = s_e1[(r0 + 1) * 68 + c + 1]; x2 = s_e1[(r0 + 1) * 68 + c + 2];
        float rmb = fmaxf(fmaxf(x0, x1), x2);
        float* dA = g_bufA + plane * PSZ + BOFF;
        for (int r = r0; r < r0 + 16; ++r) {
            x0 = s_e1[(r + 2) * 68 + c]; x1 = s_e1[(r + 2) * 68 + c + 1]; x2 = s_e1[(r + 2) * 68 + c + 2];
            const float rmc = fmaxf(fmaxf(x0, x1), x2);
            const float open_ = fmaxf(fmaxf(rma, rmb), rmc);
            const float img = s_img[(r + 2) * 70 + c + 2];
            g_skel[plane * PLANE + (by + r) * W + (bx + c)] = gelu_exact(img - open_);
            dA[(by + r) * GP + (bx + c)] = img;
            rma = rmb; rmb = rmc;
        }
    }
}

__global__ __launch_bounds__(NT) void init_kernel(const float* __restrict__ yt,
                                                  const float* __restrict__ yp) {
    __shared__ __align__(16) float s_img[70 * 70];
    __shared__ __align__(16) float s_e1[68 * 68];
    const int plane = blockIdx.z;
    const float* src = ((plane < HALF) ? yp : yt) + (plane & 15) * PLANE;
    const int by = blockIdx.y * 64, bx = blockIdx.x * 64;
    const bool border = (blockIdx.x == 0) | (blockIdx.x == 7) | (blockIdx.y == 0) | (blockIdx.y == 7);
    if (border) init_body<true >(src, s_img, s_e1, plane, by, bx, threadIdx.x, threadIdx.y);
    else        init_body<false>(src, s_img, s_e1, plane, by, bx, threadIdx.x, threadIdx.y);
}

// ---------------------------------------------------------------------------
// Fused 4-step kernel building blocks — pairwise (float2), block (32,8).
// ---------------------------------------------------------------------------
template<int DIN, int HOUT, bool BORDER>
__device__ __forceinline__ void erode_pair(const float* __restrict__ in,
                                           float* __restrict__ out,
                                           int by, int bx, int tx, int ty, int tid) {
    constexpr int DOUT = DIN - 2;
    constexpr int RPT = (DOUT + 7) / 8;
    const int j = 2 * tx;
    const int r0 = ty * RPT;
    int r1 = r0 + RPT; if (r1 > DOUT) r1 = DOUT;
    const float* pin = in + r0 * DIN + j;
    float2 a0 = *(const float2*)(pin),       a1 = *(const float2*)(pin + 2);
    float2 b0 = *(const float2*)(pin + DIN), b1 = *(const float2*)(pin + DIN + 2);
    const float* nrow = pin + 2 * DIN;
    float* orow = out + r0 * DOUT + j;
    bool c0ok = true, c1ok = true;
    if (BORDER) {
        c0ok = (unsigned)(bx + j - HOUT) < 512u;
        c1ok = (unsigned)(bx + j + 1 - HOUT) < 512u;
    }
    for (int i = r0; i < r1; ++i) {
        const float2 c0 = *(const float2*)(nrow), c1 = *(const float2*)(nrow + 2);
        const float v1 = fminf(fminf(a0.y, b0.y), c0.y);   // vert min col j+1
        const float v2 = fminf(fminf(a1.x, b1.x), c1.x);   // vert min col j+2
        float o0 = fminf(v1, fminf(b0.x, b1.x));
        float o1 = fminf(v2, fminf(b0.y, b1.y));
        if (BORDER) {
            const bool rok = (unsigned)(by + i - HOUT) < 512u;
            if (!rok | !c0ok) o0 = BIGF;
            if (!rok | !c1ok) o1 = BIGF;
        }
        *(float2*)orow = make_float2(o0, o1);
        a0 = b0; a1 = b1; b0 = c0; b1 = c1;
        nrow += DIN; orow += DOUT;
    }
    constexpr int EX = (DOUT - 64) * DOUT;
    for (int e = tid; e < EX; e += NT) {
        const int q = e / DOUT, jj = 64 + q, i = e - q * DOUT;
        float v = fminf(fminf(in[i * DIN + jj + 1], in[(i + 1) * DIN + jj + 1]),
                        in[(i + 2) * DIN + jj + 1]);
        v = fminf(v, fminf(in[(i + 1) * DIN + jj], in[(i + 1) * DIN + jj + 2]));
        if (BORDER) {
            const int gr = by + i - HOUT, gc = bx + jj - HOUT;
            if ((unsigned)gr >= 512u || (unsigned)gc >= 512u) v = BIGF;
        }
        out[i * DOUT + jj] = v;
    }
}

template<int DK, int HK, bool BORDER>
__device__ __forceinline__ void upd_pair(const float* __restrict__ ek,
                                         const float* __restrict__ ek1,
                                         float2* sk, int by, int bx, int tx, int ty) {
    constexpr int DK1 = DK - 2, H1 = HK - 1;
    const int j = 2 * tx, r0 = ty * 8;
    bool okL = true, okR = true;
    if (BORDER) {
        okL = (unsigned)(bx + j - 1) < 512u;
        okR = (unsigned)(bx + j + 2) < 512u;
    }
    auto rowpair = [&](int ri, bool rok) -> float2 {
        const float* p = ek1 + ri * DK1 + (j + H1 - 1);
        float v0, v1, v2, v3;
        if constexpr ((H1 & 1) == 1) {
            const float2 u = *(const float2*)(p);
            const float2 w = *(const float2*)(p + 2);
            v0 = u.x; v1 = u.y; v2 = w.x; v3 = w.y;
        } else {
            const float2 u = *(const float2*)(p + 1);
            v0 = p[0]; v1 = u.x; v2 = u.y; v3 = p[3];
        }
        if (BORDER) { if (!okL) v0 = -BIGF; if (!okR) v3 = -BIGF; }
        const float m = fmaxf(v1, v2);
        float2 rm = make_float2(fmaxf(m, v0), fmaxf(m, v3));
        if (BORDER && !rok) { rm.x = -BIGF; rm.y = -BIGF; }
        return rm;
    };
    float2 rma = rowpair(r0 + H1 - 1, !BORDER || ((unsigned)(by + r0 - 1) < 512u));
    float2 rmb = rowpair(r0 + H1, true);
    #pragma unroll
    for (int q = 0; q < 8; ++q) {
        const int r = r0 + q;
        const float2 rmc = rowpair(r + H1 + 1, !BORDER || ((unsigned)(by + r + 1) < 512u));
        const float o0 = fmaxf(fmaxf(rma.x, rmb.x), rmc.x);
        const float o1 = fmaxf(fmaxf(rma.y, rmb.y), rmc.y);
        const float* pc = ek + (r + HK) * DK + (j + HK);
        float e0, e1;
        if constexpr ((HK & 1) == 0) { const float2 u = *(const float2*)pc; e0 = u.x; e1 = u.y; }
        else { e0 = pc[0]; e1 = pc[1]; }
        const float2 d = gelu2(e0 - o0, e1 - o1);
        float s0 = sk[q].x, s1 = sk[q].y;
        const float2 g = gelu2(d.x - s0 * d.x, d.y - s1 * d.y);
        s0 += g.x;
        s1 += g.y;
        sk[q] = make_float2(s0, s1);
        rma = rmb; rmb = rmc;
    }
}

__device__ __forceinline__ float warpSum(float v) {
    #pragma unroll
    for (int o = 16; o; o >>= 1) v += __shfl_down_sync(0xffffffffu, v, o);
    return v;
}

// 4 fused soft-skel iterations. x (halo 6) -> E1..E5; skel in 8 float2 regs.
template<bool BORDER, bool RED>
__device__ __forceinline__ void fused_body(const float* __restrict__ sp,
                                           float* __restrict__ dp,
                                           const float* __restrict__ yt,
                                           const float* __restrict__ yp,
                                           float* sX, float* sY, float* s_red,
                                           int plane, int by, int bx,
                                           int tx, int ty) {
    const int tid = ty * 32 + tx;

    // Load x with halo 6 from padded global — zero predicates, float2.
    {
        const float* g0 = sp + (by - 6) * GP + (bx - 6);
        for (int r = ty; r < 76; r += 8) {
            const float2* grp = (const float2*)(g0 + r * GP);
            float2* srow = (float2*)(sX + r * 76);
            srow[tx] = grp[tx];
            if (tx < 6) srow[tx + 32] = grp[tx + 32];
        }
    }
    __syncthreads();

    erode_pair<76, 5, BORDER>(sX, sY, by, bx, tx, ty, tid);   // E1 (74, h5)
    __syncthreads();
    erode_pair<74, 4, BORDER>(sY, sX, by, bx, tx, ty, tid);   // E2 (72, h4)
    __syncthreads();

    float2 sk[8];
    const int r0 = ty * 8, j = 2 * tx;
    {
        const float* gs = &g_skel[plane * PLANE + (by + r0) * W + bx + j];
        #pragma unroll
        for (int q = 0; q < 8; ++q) sk[q] = *(const float2*)(gs + q * W);
    }
    upd_pair<74, 5, BORDER>(sY, sX, sk, by, bx, tx, ty);      // step 1
    __syncthreads();
    erode_pair<72, 3, BORDER>(sX, sY, by, bx, tx, ty, tid);   // E3 (70, h3)
    __syncthreads();
    upd_pair<72, 4, BORDER>(sX, sY, sk, by, bx, tx, ty);      // step 2
    __syncthreads();
    erode_pair<70, 2, BORDER>(sY, sX, by, bx, tx, ty, tid);   // E4 (68, h2)
    __syncthreads();
    upd_pair<70, 3, BORDER>(sY, sX, sk, by, bx, tx, ty);      // step 3
    __syncthreads();
    erode_pair<68, 1, BORDER>(sX, sY, by, bx, tx, ty, tid);   // E5 (66, h1)
    __syncthreads();
    upd_pair<68, 2, BORDER>(sX, sY, sk, by, bx, tx, ty);      // step 4

    if (!RED) {
        float* gs = &g_skel[plane * PLANE + (by + r0) * W + bx + j];
        float* gd = dp + (by + r0) * GP + bx + j;
        #pragma unroll
        for (int q = 0; q < 8; ++q) {
            *(float2*)(gs + q * W) = sk[q];
            *(float2*)(gd + q * GP) = *(const float2*)(sX + (r0 + q + 2) * 68 + j + 2);
        }
    } else {
        float a0 = 0.f, a1 = 0.f, a2 = 0.f, a3 = 0.f, a4 = 0.f, a5 = 0.f, a6 = 0.f;
        const int gi0 = (plane & 15) * PLANE + (by + r0) * W + bx + j;
        if (plane < HALF) {
            #pragma unroll
            for (int q = 0; q < 8; ++q) {
                const float2 t = *(const float2*)(yt + gi0 + q * W);
                const float2 p = *(const float2*)(yp + gi0 + q * W);
                const float2 s = sk[q];
                a0 += t.x + t.y;
                a1 += p.x + p.y;
                a2 += t.x * p.x + t.y * p.y;
                a3 += s.x + s.y;
                a4 += s.x * t.x + s.y * t.y;
            }
        } else {
            #pragma unroll
            for (int q = 0; q < 8; ++q) {
                const float2 p = *(const float2*)(yp + gi0 + q * W);
                const float2 s = sk[q];
                a5 += s.x + s.y;
                a6 += s.x * p.x + s.y * p.y;
            }
        }
        float v[7] = {a0, a1, a2, a3, a4, a5, a6};
        const int lane = tid & 31, wrp = tid >> 5;
        #pragma unroll
        for (int k = 0; k < 7; k++) {
            const float s = warpSum(v[k]);
            if (lane == 0) s_red[wrp * 8 + k] = s;
        }
        __syncthreads();
        if (wrp == 0) {
            const int bid = plane * 64 + (by >> 6) * 8 + (bx >> 6);
            #pragma unroll
            for (int k = 0; k < 7; k++) {
                float s = (lane < 8) ? s_red[lane * 8 + k] : 0.f;
                s = warpSum(s);
                if (lane == 0) g_part[bid * 8 + k] = s;
            }
        }
    }
}

__global__ __launch_bounds__(NT, 5) void fused_kernel(int readA) {
    __shared__ __align__(16) float sX[76 * 76];
    __shared__ __align__(16) float sY[74 * 74];
    const float* src = readA ? g_bufA : g_bufB;
    float* dst = readA ? g_bufB : g_bufA;
    const int plane = blockIdx.z;
    const int by = blockIdx.y * 64, bx = blockIdx.x * 64;
    const float* sp = src + plane * PSZ + BOFF;
    float* dp = dst + plane * PSZ + BOFF;
    const bool border = (blockIdx.x == 0) | (blockIdx.x == 7) | (blockIdx.y == 0) | (blockIdx.y == 7);
    if (border) fused_body<true , false>(sp, dp, nullptr, nullptr, sX, sY, nullptr,
                                         plane, by, bx, threadIdx.x, threadIdx.y);
    else        fused_body<false, false>(sp, dp, nullptr, nullptr, sX, sY, nullptr,
                                         plane, by, bx, threadIdx.x, threadIdx.y);
}

__global__ __launch_bounds__(NT, 5) void fused_red_kernel(const float* __restrict__ yt,
                                                          const float* __restrict__ yp,
                                                          int readA) {
    __shared__ __align__(16) float sX[76 * 76];
    __shared__ __align__(16) float sY[74 * 74];
    __shared__ float s_red[64];
    const float* src = readA ? g_bufA : g_bufB;
    float* dst = readA ? g_bufB : g_bufA;
    const int plane = blockIdx.z;
    const int by = blockIdx.y * 64, bx = blockIdx.x * 64;
    const float* sp = src + plane * PSZ + BOFF;
    float* dp = dst + plane * PSZ + BOFF;
    const bool border = (blockIdx.x == 0) | (blockIdx.x == 7) | (blockIdx.y == 0) | (blockIdx.y == 7);
    if (border) fused_body<true , true>(sp, dp, yt, yp, sX, sY, s_red,
                                        plane, by, bx, threadIdx.x, threadIdx.y);
    else        fused_body<false, true>(sp, dp, yt, yp, sX, sY, s_red,
                                        plane, by, bx, threadIdx.x, threadIdx.y);
}

// ---------------------------------------------------------------------------
// Final: sum 2048 partials, compute loss scalar
// ---------------------------------------------------------------------------
__global__ __launch_bounds__(256) void final_kernel(float* __restrict__ out) {
    float a[7] = {0.f, 0.f, 0.f, 0.f, 0.f, 0.f, 0.f};
    for (int b = threadIdx.x; b < NBLOCKS; b += 256) {
        #pragma unroll
        for (int j = 0; j < 7; j++) a[j] += g_part[b * 8 + j];
    }
    __shared__ float shm[8][8];
    const int lane = threadIdx.x & 31, wrp = threadIdx.x >> 5;
    #pragma unroll
    for (int j = 0; j < 7; j++) {
        const float v = warpSum(a[j]);
        if (lane == 0) shm[wrp][j] = v;
    }
    __syncthreads();
    if (wrp == 0) {
        float res[7];
        #pragma unroll
        for (int j = 0; j < 7; j++) {
            float v = (lane < 8) ? shm[lane][j] : 0.f;
            res[j] = warpSum(v);
        }
        if (lane == 0) {
            const float S_t = res[0], S_p = res[1], S_tp = res[2];
            const float S_sp = res[3], S_spt = res[4];
            const float S_st = res[5], S_stp = res[6];
            const float dice  = 1.0f - (2.0f * S_tp + 1.0f) / (S_t + S_p + 1.0f);
            const float tprec = (S_spt + 1.0f) / (S_sp + 1.0f);
            const float tsens = (S_stp + 1.0f) / (S_st + 1.0f);
            const float cl    = 1.0f - 2.0f * (tprec * tsens) / (tprec + tsens);
            out[0] = 0.7f * dice + 0.3f * cl;
        }
    }
}

// ---------------------------------------------------------------------------
extern "C" void kernel_launch(void* const* d_in, const int* in_sizes, int n_in,
                              void* d_out, int out_size) {
    const float* y_true = (const float*)d_in[0];
    const float* y_pred = (const float*)d_in[1];

    dim3 grid(8, 8, NPLANES);
    dim3 blk_init(64, 4);
    dim3 blk(32, 8);

    fill_ring_kernel<<<dim3(GR, NPLANES, 2), 64>>>();
    init_kernel<<<grid, blk_init>>>(y_true, y_pred);
    fused_kernel<<<grid, blk>>>(1);      // steps 1-4   A -> B
    fused_kernel<<<grid, blk>>>(0);      // steps 5-8   B -> A
    fused_kernel<<<grid, blk>>>(1);      // steps 9-12  A -> B
    fused_kernel<<<grid, blk>>>(0);      // steps 13-16 B -> A
    fused_red_kernel<<<grid, blk>>>(y_true, y_pred, 1);  // steps 17-20 + sums
    final_kernel<<<1, 256>>>((float*)d_out);
}